// round 2
// baseline (speedup 1.0000x reference)
#include <cuda_runtime.h>
#include <math.h>

// Problem constants
#define CD    2048   // channels
#define NCOL  512    // B*H*W columns
#define HWD   256    // H*W
#define HD    256    // head dim
#define HID   512    // mlp hidden
#define EPSV  1e-5f

// ---------------- device scratch (no allocations allowed) ----------------
__device__ float g_xbn[CD * NCOL];
__device__ float g_q[CD * NCOL];
__device__ float g_k[CD * NCOL];
__device__ float g_v[CD * NCOL];
__device__ float g_ao[CD * NCOL];
__device__ float g_x1[CD * NCOL];
__device__ float g_xbn2[CD * NCOL];
__device__ float g_h[HID * NCOL];

// log of effective key multiplicity per source row/col index (separable).
// Wr = {5,10,10,10,9,8,8,8,8,8,8,9,10,10,10,5}
__constant__ float c_lw[16] = {
    1.6094379124341003f, 2.3025850929940460f, 2.3025850929940460f, 2.3025850929940460f,
    2.1972245773362196f, 2.0794415416798357f, 2.0794415416798357f, 2.0794415416798357f,
    2.0794415416798357f, 2.0794415416798357f, 2.0794415416798357f, 2.1972245773362196f,
    2.3025850929940460f, 2.3025850929940460f, 2.3025850929940460f, 1.6094379124341003f
};

// ---------------- BN1: x(B,C,HW) -> g_xbn (C, NCOL) ----------------
__global__ void bn1_kernel(const float* __restrict__ x,
                           const float* __restrict__ g, const float* __restrict__ b,
                           const float* __restrict__ m, const float* __restrict__ v)
{
    int idx = blockIdx.x * blockDim.x + threadIdx.x;
    if (idx >= CD * NCOL) return;
    int c   = idx >> 9;       // /512
    int col = idx & 511;
    int bb  = col >> 8;
    int hw  = col & 255;
    float s  = g[c] * rsqrtf(v[c] + EPSV);
    float sh = b[c] - m[c] * s;
    g_xbn[idx] = x[((size_t)bb * CD + c) * HWD + hw] * s + sh;
}

// ---------------- generic SGEMM: Y(M,NCOL) = A(M,K) @ X(K,NCOL) + bias ----------------
// MODE 0: plain.  MODE 1: ReLU6 clip.  MODE 2: +residual, write in (B,C,HW) layout.
// BM=128, BN=64, BK=16, 256 threads, 8x4 per-thread microtile.
template <int MODE>
__global__ void gemm512(const float* __restrict__ A, const float* __restrict__ X,
                        const float* __restrict__ bias, float* __restrict__ Y,
                        const float* __restrict__ res, int M, int K)
{
    __shared__ float sA[16][132];  // [k][m]
    __shared__ float sB[16][68];   // [k][n]

    const int m0 = blockIdx.x * 128;
    const int n0 = blockIdx.y * 64;
    const int tid = threadIdx.x;
    const int tx = tid & 15;       // n groups
    const int ty = tid >> 4;       // m groups

    float acc[8][4];
#pragma unroll
    for (int i = 0; i < 8; i++)
#pragma unroll
        for (int j = 0; j < 4; j++) acc[i][j] = 0.f;

    for (int k0 = 0; k0 < K; k0 += 16) {
        // A tile: 128x16 -> transposed into sA
#pragma unroll
        for (int i = 0; i < 2; i++) {
            int idx = tid * 2 + i;           // 0..511
            int row = idx >> 2;              // 0..127
            int c4  = idx & 3;               // 0..3
            float4 av = *(const float4*)(A + (size_t)(m0 + row) * K + k0 + c4 * 4);
            sA[c4 * 4 + 0][row] = av.x;
            sA[c4 * 4 + 1][row] = av.y;
            sA[c4 * 4 + 2][row] = av.z;
            sA[c4 * 4 + 3][row] = av.w;
        }
        // B tile: 16x64
        {
            int row = tid >> 4;              // 0..15
            int c4  = tid & 15;              // 0..15
            float4 bv = *(const float4*)(X + (size_t)(k0 + row) * NCOL + n0 + c4 * 4);
            *(float4*)&sB[row][c4 * 4] = bv;
        }
        __syncthreads();
#pragma unroll
        for (int kk = 0; kk < 16; kk++) {
            float ra[8], rb[4];
            *(float4*)&ra[0] = *(float4*)&sA[kk][ty * 8];
            *(float4*)&ra[4] = *(float4*)&sA[kk][ty * 8 + 4];
            *(float4*)&rb[0] = *(float4*)&sB[kk][tx * 4];
#pragma unroll
            for (int i = 0; i < 8; i++)
#pragma unroll
                for (int j = 0; j < 4; j++) acc[i][j] += ra[i] * rb[j];
        }
        __syncthreads();
    }

#pragma unroll
    for (int i = 0; i < 8; i++) {
        int m = m0 + ty * 8 + i;
        float bm = bias[m];
        float out4[4];
#pragma unroll
        for (int j = 0; j < 4; j++) {
            int n = n0 + tx * 4 + j;
            float val = acc[i][j] + bm;
            if (MODE == 1) val = fminf(fmaxf(val, 0.f), 6.f);
            if (MODE == 2) val += res[(size_t)m * NCOL + n];
            out4[j] = val;
        }
        if (MODE == 2) {
            int n  = n0 + tx * 4;
            int bb = n >> 8;
            int hw = n & 255;
            *(float4*)(Y + ((size_t)bb * CD + m) * HWD + hw) = *(float4*)out4;
        } else {
            *(float4*)(Y + (size_t)m * NCOL + n0 + tx * 4) = *(float4*)out4;
        }
    }
}

// ---------------- fused attention: per (b, head, 64-query tile) ----------------
// energy (64x256, contract hd=256) + logW bias + softmax + AV (256x64, contract 256)
#define SPS 257            // sP row stride (floats)
#define SMEM_ATTN ((64 * SPS + 16 * 68 + 16 * 260) * 4)

__global__ void attn_kernel()
{
    extern __shared__ float sm[];
    float* sP = sm;                      // 64 x SPS : energies -> probs
    float* sQ = sm + 64 * SPS;           // 16 x 68
    float* sK = sQ + 16 * 68;            // 16 x 260
    float* sV = sQ;                      // reuse Q region in phase 2 (16 x 68)

    const int bn = blockIdx.x;           // 0..15
    const int b  = bn >> 3;
    const int n  = bn & 7;
    const int q0 = blockIdx.y * 64;
    const int tid = threadIdx.x;
    const int tx = tid & 15;
    const int ty = tid >> 4;

    const float* qh = g_q + (size_t)n * HD * NCOL + b * HWD;
    const float* kh = g_k + (size_t)n * HD * NCOL + b * HWD;
    const float* vh = g_v + (size_t)n * HD * NCOL + b * HWD;

    // ---- phase 1: energy E[q=ty*4+i][s=j*16+tx] ----
    float acc[4][16];
#pragma unroll
    for (int i = 0; i < 4; i++)
#pragma unroll
        for (int j = 0; j < 16; j++) acc[i][j] = 0.f;

    for (int k0 = 0; k0 < HD; k0 += 16) {
        {   // Q tile 16x64
            int r = tid >> 4, c4 = tid & 15;
            float4 v4 = *(const float4*)(qh + (size_t)(k0 + r) * NCOL + q0 + c4 * 4);
            *(float4*)&sQ[r * 68 + c4 * 4] = v4;
        }
#pragma unroll
        for (int i = 0; i < 4; i++) {   // K tile 16x256
            int idx = i * 256 + tid;
            int r = idx >> 6, c4 = idx & 63;
            float4 v4 = *(const float4*)(kh + (size_t)(k0 + r) * NCOL + c4 * 4);
            *(float4*)&sK[r * 260 + c4 * 4] = v4;
        }
        __syncthreads();
#pragma unroll
        for (int kk = 0; kk < 16; kk++) {
            float rq[4];
            *(float4*)rq = *(float4*)&sQ[kk * 68 + ty * 4];
            float rs[16];
#pragma unroll
            for (int j = 0; j < 16; j++) rs[j] = sK[kk * 260 + j * 16 + tx];
#pragma unroll
            for (int i = 0; i < 4; i++)
#pragma unroll
                for (int j = 0; j < 16; j++) acc[i][j] += rq[i] * rs[j];
        }
        __syncthreads();
    }
    // energies + log multiplicity into sP
#pragma unroll
    for (int i = 0; i < 4; i++) {
        int q = ty * 4 + i;
#pragma unroll
        for (int j = 0; j < 16; j++) {
            int s = j * 16 + tx;
            sP[q * SPS + s] = acc[i][j] + c_lw[s >> 4] + c_lw[s & 15];
        }
    }
    __syncthreads();

    // ---- softmax per q row (8 warps x 8 rows) ----
    {
        int warp = tid >> 5, lane = tid & 31;
        for (int r = warp * 8; r < warp * 8 + 8; r++) {
            float* row = sP + r * SPS;
            float mx = -1e30f;
#pragma unroll
            for (int s = lane; s < 256; s += 32) mx = fmaxf(mx, row[s]);
#pragma unroll
            for (int o = 16; o > 0; o >>= 1) mx = fmaxf(mx, __shfl_xor_sync(0xffffffffu, mx, o));
            float sum = 0.f;
#pragma unroll
            for (int s = lane; s < 256; s += 32) {
                float e = __expf(row[s] - mx);
                row[s] = e;
                sum += e;
            }
#pragma unroll
            for (int o = 16; o > 0; o >>= 1) sum += __shfl_xor_sync(0xffffffffu, sum, o);
            float inv = 1.f / sum;
#pragma unroll
            for (int s = lane; s < 256; s += 32) row[s] *= inv;
        }
    }
    __syncthreads();

    // ---- phase 2: O[h][q] = sum_s V[h][s] * P[q][s] ----
    float* ao = g_ao + (size_t)n * HD * NCOL + b * HWD;
    for (int h0 = 0; h0 < HD; h0 += 64) {
        float acc2[4][4];
#pragma unroll
        for (int i = 0; i < 4; i++)
#pragma unroll
            for (int j = 0; j < 4; j++) acc2[i][j] = 0.f;

        for (int s0 = 0; s0 < 256; s0 += 16) {
            {   // V tile 64h x 16s, transposed to sV[s][h]
                int hr = tid >> 2, s4 = tid & 3;
                float4 v4 = *(const float4*)(vh + (size_t)(h0 + hr) * NCOL + s0 + s4 * 4);
                sV[(s4 * 4 + 0) * 68 + hr] = v4.x;
                sV[(s4 * 4 + 1) * 68 + hr] = v4.y;
                sV[(s4 * 4 + 2) * 68 + hr] = v4.z;
                sV[(s4 * 4 + 3) * 68 + hr] = v4.w;
            }
            __syncthreads();
#pragma unroll
            for (int sl = 0; sl < 16; sl++) {
                float rv[4];
                *(float4*)rv = *(float4*)&sV[sl * 68 + ty * 4];
                float rp[4];
#pragma unroll
                for (int j = 0; j < 4; j++) rp[j] = sP[(tx * 4 + j) * SPS + s0 + sl];
#pragma unroll
                for (int i = 0; i < 4; i++)
#pragma unroll
                    for (int j = 0; j < 4; j++) acc2[i][j] += rv[i] * rp[j];
            }
            __syncthreads();
        }
#pragma unroll
        for (int i = 0; i < 4; i++) {
            int h = h0 + ty * 4 + i;
            float4 ov = make_float4(acc2[i][0], acc2[i][1], acc2[i][2], acc2[i][3]);
            *(float4*)(ao + (size_t)h * NCOL + q0 + tx * 4) = ov;
        }
    }
}

// ---------------- combine: x1 = x + xbn + gamma*ao ; xbn2 = BN2(x1) ----------------
__global__ void combine_kernel(const float* __restrict__ x, const float* __restrict__ gamma,
                               const float* __restrict__ g2, const float* __restrict__ b2,
                               const float* __restrict__ m2, const float* __restrict__ v2)
{
    int idx = blockIdx.x * blockDim.x + threadIdx.x;
    if (idx >= CD * NCOL) return;
    int c   = idx >> 9;
    int col = idx & 511;
    int bb  = col >> 8;
    int hw  = col & 255;
    float x1 = x[((size_t)bb * CD + c) * HWD + hw] + g_xbn[idx] + gamma[0] * g_ao[idx];
    g_x1[idx] = x1;
    float s  = g2[c] * rsqrtf(v2[c] + EPSV);
    g_xbn2[idx] = x1 * s + (b2[c] - m2[c] * s);
}

// ---------------- launch ----------------
extern "C" void kernel_launch(void* const* d_in, const int* in_sizes, int n_in,
                              void* d_out, int out_size)
{
    const float* x     = (const float*)d_in[0];
    const float* bn1_g = (const float*)d_in[1];
    const float* bn1_b = (const float*)d_in[2];
    const float* bn1_m = (const float*)d_in[3];
    const float* bn1_v = (const float*)d_in[4];
    const float* Wq    = (const float*)d_in[5];
    const float* bq    = (const float*)d_in[6];
    const float* Wk    = (const float*)d_in[7];
    const float* bk    = (const float*)d_in[8];
    const float* Wv    = (const float*)d_in[9];
    const float* bv    = (const float*)d_in[10];
    const float* gamma = (const float*)d_in[11];
    const float* bn2_g = (const float*)d_in[12];
    const float* bn2_b = (const float*)d_in[13];
    const float* bn2_m = (const float*)d_in[14];
    const float* bn2_v = (const float*)d_in[15];
    const float* W1    = (const float*)d_in[16];
    const float* b1    = (const float*)d_in[17];
    const float* W2    = (const float*)d_in[18];
    const float* b2    = (const float*)d_in[19];
    float* out = (float*)d_out;

    float* p_xbn;  cudaGetSymbolAddress((void**)&p_xbn,  g_xbn);
    float* p_q;    cudaGetSymbolAddress((void**)&p_q,    g_q);
    float* p_k;    cudaGetSymbolAddress((void**)&p_k,    g_k);
    float* p_v;    cudaGetSymbolAddress((void**)&p_v,    g_v);
    float* p_x1;   cudaGetSymbolAddress((void**)&p_x1,   g_x1);
    float* p_xbn2; cudaGetSymbolAddress((void**)&p_xbn2, g_xbn2);
    float* p_h;    cudaGetSymbolAddress((void**)&p_h,    g_h);

    // BN1
    bn1_kernel<<<(CD * NCOL) / 256, 256>>>(x, bn1_g, bn1_b, bn1_m, bn1_v);

    // Q/K/V projections (on source positions only — reflect pad handled by multiplicity)
    dim3 gproj(CD / 128, NCOL / 64);
    gemm512<0><<<gproj, 256>>>(Wq, p_xbn, bq, p_q, nullptr, CD, CD);
    gemm512<0><<<gproj, 256>>>(Wk, p_xbn, bk, p_k, nullptr, CD, CD);
    gemm512<0><<<gproj, 256>>>(Wv, p_xbn, bv, p_v, nullptr, CD, CD);

    // Attention (collapsed to 256 distinct keys with log-multiplicity bias)
    cudaFuncSetAttribute(attn_kernel, cudaFuncAttributeMaxDynamicSharedMemorySize, SMEM_ATTN);
    attn_kernel<<<dim3(16, 4), 256, SMEM_ATTN>>>();

    // residual 1 + BN2
    combine_kernel<<<(CD * NCOL) / 256, 256>>>(x, gamma, bn2_g, bn2_b, bn2_m, bn2_v);

    // MLP
    gemm512<1><<<dim3(HID / 128, NCOL / 64), 256>>>(W1, p_xbn2, b1, p_h, nullptr, HID, CD);
    gemm512<2><<<dim3(CD / 128, NCOL / 64), 256>>>(W2, p_h, b2, out, p_x1, CD, HID);
}

// round 4
// speedup vs baseline: 2.1101x; 2.1101x over previous
#include <cuda_runtime.h>
#include <cuda_bf16.h>
#include <cstdint>
#include <math.h>

#define CD    2048
#define NCOL  512
#define HWD   256
#define HD    256
#define HID   512
#define EPSV  1e-5f

typedef __nv_bfloat16 bf16;

// ---------------- device scratch ----------------
__device__ float g_xbn [CD * NCOL];            // BN1 output, [C][NCOL] fp32
__device__ bf16  g_xth [NCOL * CD];            // BN1 output transposed hi (row n, col c)
__device__ bf16  g_xtl [NCOL * CD];
__device__ bf16  g_wh  [3 * CD * CD];          // Wq|Wk|Wv hi (row m, col k)
__device__ bf16  g_wl  [3 * CD * CD];
__device__ bf16  g_w1h [HID * CD];
__device__ bf16  g_w1l [HID * CD];
__device__ bf16  g_w2h [CD * HID];
__device__ bf16  g_w2l [CD * HID];
__device__ float g_bqkv[3 * CD];
__device__ float g_qkv [3 * CD * NCOL];        // q|k|v fp32 [3C][NCOL]
__device__ float g_ao  [CD * NCOL];
__device__ float g_x1  [CD * NCOL];
__device__ bf16  g_xt2h[NCOL * CD];            // BN2 output transposed hi
__device__ bf16  g_xt2l[NCOL * CD];
__device__ float g_h   [HID * NCOL];           // MLP hidden fp32
__device__ bf16  g_hth [NCOL * HID];           // hidden transposed hi
__device__ bf16  g_htl [NCOL * HID];

// log key multiplicity (separable reflect-pad collapse)
__constant__ float c_lw[16] = {
    1.6094379124341003f, 2.3025850929940460f, 2.3025850929940460f, 2.3025850929940460f,
    2.1972245773362196f, 2.0794415416798357f, 2.0794415416798357f, 2.0794415416798357f,
    2.0794415416798357f, 2.0794415416798357f, 2.0794415416798357f, 2.1972245773362196f,
    2.3025850929940460f, 2.3025850929940460f, 2.3025850929940460f, 1.6094379124341003f
};

// ---------------- PTX helpers (sm_80-compatible only) ----------------
__device__ __forceinline__ uint32_t smem_u32(const void* p) {
    uint32_t a;
    asm("{ .reg .u64 t; cvta.to.shared.u64 t, %1; cvt.u32.u64 %0, t; }" : "=r"(a) : "l"(p));
    return a;
}
__device__ __forceinline__ void cp_async16(uint32_t sdst, const void* gsrc) {
    asm volatile("cp.async.cg.shared.global [%0], [%1], 16;" :: "r"(sdst), "l"(gsrc));
}
__device__ __forceinline__ void cp_commit() { asm volatile("cp.async.commit_group;"); }
__device__ __forceinline__ void cp_wait1()  { asm volatile("cp.async.wait_group 1;" ::: "memory"); }

#define LDSM4(r, addr) \
    asm volatile("ldmatrix.sync.aligned.m8n8.x4.shared.b16 {%0,%1,%2,%3}, [%4];" \
        : "=r"((r)[0]), "=r"((r)[1]), "=r"((r)[2]), "=r"((r)[3]) : "r"(addr))

#define MMA16816(d, a, b) \
    asm volatile("mma.sync.aligned.m16n8k16.row.col.f32.bf16.bf16.f32 " \
        "{%0,%1,%2,%3},{%4,%5,%6,%7},{%8,%9},{%0,%1,%2,%3};" \
        : "+f"((d)[0]), "+f"((d)[1]), "+f"((d)[2]), "+f"((d)[3]) \
        : "r"((a)[0]), "r"((a)[1]), "r"((a)[2]), "r"((a)[3]), "r"((b)[0]), "r"((b)[1]))

// ---------------- BN1 + transpose + bf16 split ----------------
__global__ void bn1_t_kernel(const float* __restrict__ x,
                             const float* __restrict__ g, const float* __restrict__ b,
                             const float* __restrict__ m, const float* __restrict__ v)
{
    __shared__ float t[32][33];
    int c0 = blockIdx.x * 32, hw0 = blockIdx.y * 32, bb = blockIdx.z;
    int tx = threadIdx.x, ty = threadIdx.y;
#pragma unroll
    for (int i = 0; i < 4; i++) {
        int c = c0 + ty + i * 8;
        float s  = g[c] * rsqrtf(v[c] + EPSV);
        float sh = b[c] - m[c] * s;
        float val = x[((size_t)bb * CD + c) * HWD + hw0 + tx] * s + sh;
        g_xbn[(size_t)c * NCOL + bb * HWD + hw0 + tx] = val;
        t[ty + i * 8][tx] = val;
    }
    __syncthreads();
#pragma unroll
    for (int i = 0; i < 4; i++) {
        float val = t[tx][ty + i * 8];
        int n = bb * HWD + hw0 + ty + i * 8;
        bf16 h = __float2bfloat16_rn(val);
        g_xth[(size_t)n * CD + c0 + tx] = h;
        g_xtl[(size_t)n * CD + c0 + tx] = __float2bfloat16_rn(val - __bfloat162float(h));
    }
}

// ---------------- generic transpose + split: src[C][NCOL] f32 -> dh/dl[NCOL][C] bf16 ----------------
__global__ void tsplit_kernel(const float* __restrict__ src, bf16* __restrict__ dh,
                              bf16* __restrict__ dl, int C)
{
    __shared__ float t[32][33];
    int c0 = blockIdx.x * 32, col0 = blockIdx.y * 32;
    int tx = threadIdx.x, ty = threadIdx.y;
#pragma unroll
    for (int i = 0; i < 4; i++)
        t[ty + i * 8][tx] = src[(size_t)(c0 + ty + i * 8) * NCOL + col0 + tx];
    __syncthreads();
#pragma unroll
    for (int i = 0; i < 4; i++) {
        float val = t[tx][ty + i * 8];
        int n = col0 + ty + i * 8;
        bf16 h = __float2bfloat16_rn(val);
        dh[(size_t)n * C + c0 + tx] = h;
        dl[(size_t)n * C + c0 + tx] = __float2bfloat16_rn(val - __bfloat162float(h));
    }
}

// ---------------- weight hi/lo split ----------------
__global__ void wsplit_kernel(const float* __restrict__ src, bf16* __restrict__ dh,
                              bf16* __restrict__ dl, int n4)
{
    int i = blockIdx.x * blockDim.x + threadIdx.x;
    if (i >= n4) return;
    float4 v = ((const float4*)src)[i];
    bf16 h0 = __float2bfloat16_rn(v.x), h1 = __float2bfloat16_rn(v.y);
    bf16 h2 = __float2bfloat16_rn(v.z), h3 = __float2bfloat16_rn(v.w);
    bf16 l0 = __float2bfloat16_rn(v.x - __bfloat162float(h0));
    bf16 l1 = __float2bfloat16_rn(v.y - __bfloat162float(h1));
    bf16 l2 = __float2bfloat16_rn(v.z - __bfloat162float(h2));
    bf16 l3 = __float2bfloat16_rn(v.w - __bfloat162float(h3));
    uint2 ph, pl;
    ph.x = ((uint32_t)__bfloat16_as_ushort(h1) << 16) | __bfloat16_as_ushort(h0);
    ph.y = ((uint32_t)__bfloat16_as_ushort(h3) << 16) | __bfloat16_as_ushort(h2);
    pl.x = ((uint32_t)__bfloat16_as_ushort(l1) << 16) | __bfloat16_as_ushort(l0);
    pl.y = ((uint32_t)__bfloat16_as_ushort(l3) << 16) | __bfloat16_as_ushort(l2);
    ((uint2*)dh)[i] = ph;
    ((uint2*)dl)[i] = pl;
}

__global__ void concat_bias_kernel(const float* __restrict__ a, const float* __restrict__ c,
                                   const float* __restrict__ e)
{
    int i = blockIdx.x * blockDim.x + threadIdx.x;
    if (i >= CD) return;
    g_bqkv[i] = a[i];
    g_bqkv[CD + i] = c[i];
    g_bqkv[2 * CD + i] = e[i];
}

// ---------------- warp-MMA split-bf16 GEMM ----------------
// D(M, 512) = [Ah+Al](M,K) @ [Bh+Bl](512,K)^T + bias, fp32 accumulate.
// Tiles: BM x 128, BK=32, double-buffered cp.async, 8 warps.
// Smem per operand: rows x 40 bf16 (80B stride -> conflict-free ldmatrix).
// EPI 0: +bias -> Y[m][NCOL]      (QKV)
// EPI 1: ReLU6(+bias) -> Y fp32   (MLP1)
// EPI 2: +bias +res -> (B,C,HW)   (MLP2)
template <int BM, int EPI>
__global__ void __launch_bounds__(256) gemm_mma(
    const bf16* __restrict__ Ah, const bf16* __restrict__ Al,
    const bf16* __restrict__ Bh, const bf16* __restrict__ Bl,
    const float* __restrict__ bias, float* __restrict__ Y,
    const float* __restrict__ res, int K)
{
    constexpr int ABYT  = BM * 80;            // one A operand bytes (stride 40 bf16)
    constexpr int BBYT  = 128 * 80;           // one B operand bytes
    constexpr int STAGE = 2 * ABYT + 2 * BBYT;
    constexpr int WM = BM / 32;               // warps along m
    constexpr int WN = 8 / WM;                // warps along n
    constexpr int NI = (128 / WN) / 8;        // 8-wide n tiles per warp

    extern __shared__ __align__(16) char dsm[];
    const uint32_t sbase = smem_u32(dsm);

    const int tid  = threadIdx.x;
    const int wid  = tid >> 5;
    const int lane = tid & 31;
    const int wm   = wid % WM;
    const int wn   = wid / WM;
    const int m0   = blockIdx.x * BM;
    const int n0   = blockIdx.y * 128;

    const bf16* pAh = Ah + (size_t)m0 * K;
    const bf16* pAl = Al + (size_t)m0 * K;
    const bf16* pBh = Bh + (size_t)n0 * K;
    const bf16* pBl = Bl + (size_t)n0 * K;

    float acc[2][NI][4];
#pragma unroll
    for (int mi = 0; mi < 2; mi++)
#pragma unroll
        for (int ni = 0; ni < NI; ni++)
#pragma unroll
            for (int j = 0; j < 4; j++) acc[mi][ni][j] = 0.f;

    const int nch = K >> 5;   // 32-wide k chunks

    auto load_stage = [&](int slot, int ko) {
        const uint32_t st = sbase + slot * STAGE;
        for (int i = tid; i < BM * 4; i += 256) {
            int row = i >> 2, seg = i & 3;
            cp_async16(st + row * 80 + seg * 16, pAh + (size_t)row * K + ko + seg * 8);
        }
        for (int i = tid; i < BM * 4; i += 256) {
            int row = i >> 2, seg = i & 3;
            cp_async16(st + ABYT + row * 80 + seg * 16, pAl + (size_t)row * K + ko + seg * 8);
        }
        for (int i = tid; i < 512; i += 256) {
            int row = i >> 2, seg = i & 3;
            cp_async16(st + 2 * ABYT + row * 80 + seg * 16, pBh + (size_t)row * K + ko + seg * 8);
        }
        for (int i = tid; i < 512; i += 256) {
            int row = i >> 2, seg = i & 3;
            cp_async16(st + 2 * ABYT + BBYT + row * 80 + seg * 16, pBl + (size_t)row * K + ko + seg * 8);
        }
    };

    load_stage(0, 0);  cp_commit();
    load_stage(1, 32); cp_commit();

    const int lrow = (lane & 7) + ((lane >> 3) & 1) * 8;   // row within 16-row tile
    const int lcol = (lane >> 4) * 8;                      // k sub-block 0/8

    for (int ch = 0; ch < nch; ch++) {
        cp_wait1();
        __syncthreads();
        const uint32_t st = sbase + (ch & 1) * STAGE;

#pragma unroll
        for (int ks = 0; ks < 32; ks += 16) {
            uint32_t ah[2][4], al[2][4];
#pragma unroll
            for (int mi = 0; mi < 2; mi++) {
                uint32_t addr = st + (wm * 32 + mi * 16 + lrow) * 80 + (ks + lcol) * 2;
                LDSM4(ah[mi], addr);
                LDSM4(al[mi], addr + ABYT);
            }
            uint32_t bh[NI][2], bl[NI][2];
#pragma unroll
            for (int np = 0; np < NI / 2; np++) {
                uint32_t addr = st + 2 * ABYT + (wn * (NI * 8) + np * 16 + lrow) * 80 + (ks + lcol) * 2;
                uint32_t r[4];
                LDSM4(r, addr);
                bh[2 * np][0] = r[0]; bh[2 * np][1] = r[2];
                bh[2 * np + 1][0] = r[1]; bh[2 * np + 1][1] = r[3];
                LDSM4(r, addr + BBYT);
                bl[2 * np][0] = r[0]; bl[2 * np][1] = r[2];
                bl[2 * np + 1][0] = r[1]; bl[2 * np + 1][1] = r[3];
            }
#pragma unroll
            for (int mi = 0; mi < 2; mi++)
#pragma unroll
                for (int ni = 0; ni < NI; ni++) {
                    MMA16816(acc[mi][ni], ah[mi], bh[ni]);
                    MMA16816(acc[mi][ni], ah[mi], bl[ni]);
                    MMA16816(acc[mi][ni], al[mi], bh[ni]);
                }
        }
        __syncthreads();
        if (ch + 2 < nch) load_stage(ch & 1, (ch + 2) * 32);
        cp_commit();
    }

    // ---- epilogue ----
#pragma unroll
    for (int mi = 0; mi < 2; mi++) {
        int r0 = m0 + wm * 32 + mi * 16 + (lane >> 2);
        float bv0 = bias[r0], bv1 = bias[r0 + 8];
#pragma unroll
        for (int ni = 0; ni < NI; ni++) {
            int c = n0 + wn * (NI * 8) + ni * 8 + (lane & 3) * 2;
            float* a = acc[mi][ni];
            if (EPI == 0 || EPI == 1) {
                float2 v0 = make_float2(a[0] + bv0, a[1] + bv0);
                float2 v1 = make_float2(a[2] + bv1, a[3] + bv1);
                if (EPI == 1) {
                    v0.x = fminf(fmaxf(v0.x, 0.f), 6.f);
                    v0.y = fminf(fmaxf(v0.y, 0.f), 6.f);
                    v1.x = fminf(fmaxf(v1.x, 0.f), 6.f);
                    v1.y = fminf(fmaxf(v1.y, 0.f), 6.f);
                }
                *(float2*)(Y + (size_t)r0 * NCOL + c) = v0;
                *(float2*)(Y + (size_t)(r0 + 8) * NCOL + c) = v1;
            } else {
                int bb = c >> 8, hw = c & 255;
                const float* rp0 = res + (size_t)r0 * NCOL + c;
                const float* rp1 = res + (size_t)(r0 + 8) * NCOL + c;
                float2 v0 = make_float2(a[0] + bv0 + rp0[0], a[1] + bv0 + rp0[1]);
                float2 v1 = make_float2(a[2] + bv1 + rp1[0], a[3] + bv1 + rp1[1]);
                *(float2*)(Y + ((size_t)bb * CD + r0) * HWD + hw) = v0;
                *(float2*)(Y + ((size_t)bb * CD + r0 + 8) * HWD + hw) = v1;
            }
        }
    }
}

// ---------------- fused attention (fp32, collapsed keys) ----------------
#define SPS 257
#define SMEM_ATTN ((64 * SPS + 16 * 68 + 16 * 260) * 4)

__global__ void attn_kernel()
{
    extern __shared__ float sm[];
    float* sP = sm;
    float* sQ = sm + 64 * SPS;
    float* sK = sQ + 16 * 68;
    float* sV = sQ;

    const int bn = blockIdx.x;
    const int b  = bn >> 3;
    const int n  = bn & 7;
    const int q0 = blockIdx.y * 64;
    const int tid = threadIdx.x;
    const int tx = tid & 15;
    const int ty = tid >> 4;

    const float* qh = g_qkv + (size_t)n * HD * NCOL + b * HWD;
    const float* kh = g_qkv + (size_t)CD * NCOL + (size_t)n * HD * NCOL + b * HWD;
    const float* vh = g_qkv + (size_t)2 * CD * NCOL + (size_t)n * HD * NCOL + b * HWD;

    float acc[4][16];
#pragma unroll
    for (int i = 0; i < 4; i++)
#pragma unroll
        for (int j = 0; j < 16; j++) acc[i][j] = 0.f;

    for (int k0 = 0; k0 < HD; k0 += 16) {
        {
            int r = tid >> 4, c4 = tid & 15;
            float4 v4 = *(const float4*)(qh + (size_t)(k0 + r) * NCOL + q0 + c4 * 4);
            *(float4*)&sQ[r * 68 + c4 * 4] = v4;
        }
#pragma unroll
        for (int i = 0; i < 4; i++) {
            int idx = i * 256 + tid;
            int r = idx >> 6, c4 = idx & 63;
            float4 v4 = *(const float4*)(kh + (size_t)(k0 + r) * NCOL + c4 * 4);
            *(float4*)&sK[r * 260 + c4 * 4] = v4;
        }
        __syncthreads();
#pragma unroll
        for (int kk = 0; kk < 16; kk++) {
            float rq[4];
            *(float4*)rq = *(float4*)&sQ[kk * 68 + ty * 4];
            float rs[16];
#pragma unroll
            for (int j = 0; j < 16; j++) rs[j] = sK[kk * 260 + j * 16 + tx];
#pragma unroll
            for (int i = 0; i < 4; i++)
#pragma unroll
                for (int j = 0; j < 16; j++) acc[i][j] += rq[i] * rs[j];
        }
        __syncthreads();
    }
#pragma unroll
    for (int i = 0; i < 4; i++) {
        int q = ty * 4 + i;
#pragma unroll
        for (int j = 0; j < 16; j++) {
            int s = j * 16 + tx;
            sP[q * SPS + s] = acc[i][j] + c_lw[s >> 4] + c_lw[s & 15];
        }
    }
    __syncthreads();
    {
        int warp = tid >> 5, lane = tid & 31;
        for (int r = warp * 8; r < warp * 8 + 8; r++) {
            float* row = sP + r * SPS;
            float mx = -1e30f;
#pragma unroll
            for (int s = lane; s < 256; s += 32) mx = fmaxf(mx, row[s]);
#pragma unroll
            for (int o = 16; o > 0; o >>= 1) mx = fmaxf(mx, __shfl_xor_sync(0xffffffffu, mx, o));
            float sum = 0.f;
#pragma unroll
            for (int s = lane; s < 256; s += 32) {
                float e = __expf(row[s] - mx);
                row[s] = e;
                sum += e;
            }
#pragma unroll
            for (int o = 16; o > 0; o >>= 1) sum += __shfl_xor_sync(0xffffffffu, sum, o);
            float inv = 1.f / sum;
#pragma unroll
            for (int s = lane; s < 256; s += 32) row[s] *= inv;
        }
    }
    __syncthreads();

    float* ao = g_ao + (size_t)n * HD * NCOL + b * HWD;
    for (int h0 = 0; h0 < HD; h0 += 64) {
        float acc2[4][4];
#pragma unroll
        for (int i = 0; i < 4; i++)
#pragma unroll
            for (int j = 0; j < 4; j++) acc2[i][j] = 0.f;

        for (int s0 = 0; s0 < 256; s0 += 16) {
            {
                int hr = tid >> 2, s4 = tid & 3;
                float4 v4 = *(const float4*)(vh + (size_t)(h0 + hr) * NCOL + s0 + s4 * 4);
                sV[(s4 * 4 + 0) * 68 + hr] = v4.x;
                sV[(s4 * 4 + 1) * 68 + hr] = v4.y;
                sV[(s4 * 4 + 2) * 68 + hr] = v4.z;
                sV[(s4 * 4 + 3) * 68 + hr] = v4.w;
            }
            __syncthreads();
#pragma unroll
            for (int sl = 0; sl < 16; sl++) {
                float rv[4];
                *(float4*)rv = *(float4*)&sV[sl * 68 + ty * 4];
                float rp[4];
#pragma unroll
                for (int j = 0; j < 4; j++) rp[j] = sP[(tx * 4 + j) * SPS + s0 + sl];
#pragma unroll
                for (int i = 0; i < 4; i++)
#pragma unroll
                    for (int j = 0; j < 4; j++) acc2[i][j] += rv[i] * rp[j];
            }
            __syncthreads();
        }
#pragma unroll
        for (int i = 0; i < 4; i++) {
            int h = h0 + ty * 4 + i;
            float4 ov = make_float4(acc2[i][0], acc2[i][1], acc2[i][2], acc2[i][3]);
            *(float4*)(ao + (size_t)h * NCOL + q0 + tx * 4) = ov;
        }
    }
}

// ---------------- combine: x1 = x + xbn + gamma*ao ; BN2 -> transposed hi/lo ----------------
__global__ void combine_t_kernel(const float* __restrict__ x, const float* __restrict__ gamma,
                                 const float* __restrict__ g2, const float* __restrict__ b2,
                                 const float* __restrict__ m2, const float* __restrict__ v2)
{
    __shared__ float t[32][33];
    int c0 = blockIdx.x * 32, col0 = blockIdx.y * 32;
    int tx = threadIdx.x, ty = threadIdx.y;
    int col = col0 + tx;
    int bb = col >> 8, hw = col & 255;
    float gm = gamma[0];
#pragma unroll
    for (int i = 0; i < 4; i++) {
        int c = c0 + ty + i * 8;
        size_t idx = (size_t)c * NCOL + col;
        float x1 = x[((size_t)bb * CD + c) * HWD + hw] + g_xbn[idx] + gm * g_ao[idx];
        g_x1[idx] = x1;
        float s = g2[c] * rsqrtf(v2[c] + EPSV);
        t[ty + i * 8][tx] = x1 * s + (b2[c] - m2[c] * s);
    }
    __syncthreads();
#pragma unroll
    for (int i = 0; i < 4; i++) {
        float val = t[tx][ty + i * 8];
        int n = col0 + ty + i * 8;
        bf16 h = __float2bfloat16_rn(val);
        g_xt2h[(size_t)n * CD + c0 + tx] = h;
        g_xt2l[(size_t)n * CD + c0 + tx] = __float2bfloat16_rn(val - __bfloat162float(h));
    }
}

// ---------------- launch ----------------
extern "C" void kernel_launch(void* const* d_in, const int* in_sizes, int n_in,
                              void* d_out, int out_size)
{
    const float* x     = (const float*)d_in[0];
    const float* bn1_g = (const float*)d_in[1];
    const float* bn1_b = (const float*)d_in[2];
    const float* bn1_m = (const float*)d_in[3];
    const float* bn1_v = (const float*)d_in[4];
    const float* Wq    = (const float*)d_in[5];
    const float* bq    = (const float*)d_in[6];
    const float* Wk    = (const float*)d_in[7];
    const float* bk    = (const float*)d_in[8];
    const float* Wv    = (const float*)d_in[9];
    const float* bv    = (const float*)d_in[10];
    const float* gamma = (const float*)d_in[11];
    const float* bn2_g = (const float*)d_in[12];
    const float* bn2_b = (const float*)d_in[13];
    const float* bn2_m = (const float*)d_in[14];
    const float* bn2_v = (const float*)d_in[15];
    const float* W1    = (const float*)d_in[16];
    const float* b1    = (const float*)d_in[17];
    const float* W2    = (const float*)d_in[18];
    const float* b2    = (const float*)d_in[19];
    float* out = (float*)d_out;

    bf16 *p_wh, *p_wl, *p_w1h, *p_w1l, *p_w2h, *p_w2l, *p_xth, *p_xtl, *p_x2h, *p_x2l, *p_hth, *p_htl;
    float *p_bqkv, *p_qkv, *p_x1, *p_h;
    cudaGetSymbolAddress((void**)&p_wh,  g_wh);
    cudaGetSymbolAddress((void**)&p_wl,  g_wl);
    cudaGetSymbolAddress((void**)&p_w1h, g_w1h);
    cudaGetSymbolAddress((void**)&p_w1l, g_w1l);
    cudaGetSymbolAddress((void**)&p_w2h, g_w2h);
    cudaGetSymbolAddress((void**)&p_w2l, g_w2l);
    cudaGetSymbolAddress((void**)&p_xth, g_xth);
    cudaGetSymbolAddress((void**)&p_xtl, g_xtl);
    cudaGetSymbolAddress((void**)&p_x2h, g_xt2h);
    cudaGetSymbolAddress((void**)&p_x2l, g_xt2l);
    cudaGetSymbolAddress((void**)&p_hth, g_hth);
    cudaGetSymbolAddress((void**)&p_htl, g_htl);
    cudaGetSymbolAddress((void**)&p_bqkv, g_bqkv);
    cudaGetSymbolAddress((void**)&p_qkv, g_qkv);
    cudaGetSymbolAddress((void**)&p_x1,  g_x1);
    cudaGetSymbolAddress((void**)&p_h,   g_h);

    constexpr int SM128 = 2 * (2 * 128 * 80 + 2 * 128 * 80);  // 81920
    constexpr int SM64  = 2 * (2 * 64 * 80 + 2 * 128 * 80);   // 61440
    cudaFuncSetAttribute(gemm_mma<128, 0>, cudaFuncAttributeMaxDynamicSharedMemorySize, SM128);
    cudaFuncSetAttribute(gemm_mma<64, 1>,  cudaFuncAttributeMaxDynamicSharedMemorySize, SM64);
    cudaFuncSetAttribute(gemm_mma<128, 2>, cudaFuncAttributeMaxDynamicSharedMemorySize, SM128);
    cudaFuncSetAttribute(attn_kernel, cudaFuncAttributeMaxDynamicSharedMemorySize, SMEM_ATTN);

    // BN1 (+ transpose + split)
    bn1_t_kernel<<<dim3(CD / 32, HWD / 32, 2), dim3(32, 8)>>>(x, bn1_g, bn1_b, bn1_m, bn1_v);

    // weight splits
    wsplit_kernel<<<(CD * CD / 4 + 255) / 256, 256>>>(Wq, p_wh, p_wl, CD * CD / 4);
    wsplit_kernel<<<(CD * CD / 4 + 255) / 256, 256>>>(Wk, p_wh + (size_t)CD * CD, p_wl + (size_t)CD * CD, CD * CD / 4);
    wsplit_kernel<<<(CD * CD / 4 + 255) / 256, 256>>>(Wv, p_wh + (size_t)2 * CD * CD, p_wl + (size_t)2 * CD * CD, CD * CD / 4);
    wsplit_kernel<<<(HID * CD / 4 + 255) / 256, 256>>>(W1, p_w1h, p_w1l, HID * CD / 4);
    wsplit_kernel<<<(CD * HID / 4 + 255) / 256, 256>>>(W2, p_w2h, p_w2l, CD * HID / 4);
    concat_bias_kernel<<<CD / 256, 256>>>(bq, bk, bv);

    // QKV fused projection: M = 6144, N = 512, K = 2048
    gemm_mma<128, 0><<<dim3(48, 4), 256, SM128>>>(p_wh, p_wl, p_xth, p_xtl, p_bqkv, p_qkv, nullptr, CD);

    // attention (collapsed keys + log-multiplicity bias)
    attn_kernel<<<dim3(16, 4), 256, SMEM_ATTN>>>();

    // residual + BN2 (+ transpose + split)
    combine_t_kernel<<<dim3(CD / 32, NCOL / 32), dim3(32, 8)>>>(x, gamma, bn2_g, bn2_b, bn2_m, bn2_v);

    // MLP1: 512 x 512, K=2048, ReLU6 -> fp32 hidden
    gemm_mma<64, 1><<<dim3(HID / 64, 4), 256, SM64>>>(p_w1h, p_w1l, p_x2h, p_x2l, b1, p_h, nullptr, CD);

    // hidden transpose + split
    tsplit_kernel<<<dim3(HID / 32, NCOL / 32), dim3(32, 8)>>>(p_h, p_hth, p_htl, HID);

    // MLP2: 2048 x 512, K=512, +residual, NCHW out
    gemm_mma<128, 2><<<dim3(CD / 128, 4), 256, SM128>>>(p_w2h, p_w2l, p_hth, p_htl, b2, out, p_x1, HID);
}

// round 5
// speedup vs baseline: 2.2233x; 1.0536x over previous
#include <cuda_runtime.h>
#include <cuda_bf16.h>
#include <cstdint>
#include <math.h>

#define CD    2048
#define NCOL  512
#define HWD   256
#define HD    256
#define HID   512
#define EPSV  1e-5f

typedef __nv_bfloat16 bf16;

// ---------------- device scratch ----------------
__device__ float g_xbn [CD * NCOL];            // BN1 output, [C][NCOL] fp32
__device__ bf16  g_xth [NCOL * CD];            // BN1 output transposed hi (row n, col c)
__device__ bf16  g_xtl [NCOL * CD];
__device__ bf16  g_wh  [3 * CD * CD];          // Wq|Wk|Wv hi (row m, col k)
__device__ bf16  g_wl  [3 * CD * CD];
__device__ bf16  g_w1h [HID * CD];
__device__ bf16  g_w1l [HID * CD];
__device__ bf16  g_w2h [CD * HID];
__device__ bf16  g_w2l [CD * HID];
__device__ float g_bqkv[3 * CD];
__device__ float g_qkv [3 * CD * NCOL];        // q|k|v fp32 [3C][NCOL]
__device__ float g_ao  [CD * NCOL];
__device__ float g_x1  [CD * NCOL];
__device__ bf16  g_xt2h[NCOL * CD];            // BN2 output transposed hi
__device__ bf16  g_xt2l[NCOL * CD];
__device__ float g_h   [HID * NCOL];           // MLP hidden fp32
__device__ bf16  g_hth [NCOL * HID];           // hidden transposed hi
__device__ bf16  g_htl [NCOL * HID];

// log key multiplicity (separable reflect-pad collapse)
__constant__ float c_lw[16] = {
    1.6094379124341003f, 2.3025850929940460f, 2.3025850929940460f, 2.3025850929940460f,
    2.1972245773362196f, 2.0794415416798357f, 2.0794415416798357f, 2.0794415416798357f,
    2.0794415416798357f, 2.0794415416798357f, 2.0794415416798357f, 2.1972245773362196f,
    2.3025850929940460f, 2.3025850929940460f, 2.3025850929940460f, 1.6094379124341003f
};

// ---------------- PTX helpers (sm_80-compatible only) ----------------
__device__ __forceinline__ uint32_t smem_u32(const void* p) {
    uint32_t a;
    asm("{ .reg .u64 t; cvta.to.shared.u64 t, %1; cvt.u32.u64 %0, t; }" : "=r"(a) : "l"(p));
    return a;
}
__device__ __forceinline__ void cp_async16(uint32_t sdst, const void* gsrc) {
    asm volatile("cp.async.cg.shared.global [%0], [%1], 16;" :: "r"(sdst), "l"(gsrc));
}
__device__ __forceinline__ void cp_commit() { asm volatile("cp.async.commit_group;"); }
__device__ __forceinline__ void cp_wait2()  { asm volatile("cp.async.wait_group 2;" ::: "memory"); }

#define LDSM4(r, addr) \
    asm volatile("ldmatrix.sync.aligned.m8n8.x4.shared.b16 {%0,%1,%2,%3}, [%4];" \
        : "=r"((r)[0]), "=r"((r)[1]), "=r"((r)[2]), "=r"((r)[3]) : "r"(addr))

#define MMA16816(d, a, b) \
    asm volatile("mma.sync.aligned.m16n8k16.row.col.f32.bf16.bf16.f32 " \
        "{%0,%1,%2,%3},{%4,%5,%6,%7},{%8,%9},{%0,%1,%2,%3};" \
        : "+f"((d)[0]), "+f"((d)[1]), "+f"((d)[2]), "+f"((d)[3]) \
        : "r"((a)[0]), "r"((a)[1]), "r"((a)[2]), "r"((a)[3]), "r"((b)[0]), "r"((b)[1]))

// ---------------- BN1 + transpose + bf16 split ----------------
__global__ void bn1_t_kernel(const float* __restrict__ x,
                             const float* __restrict__ g, const float* __restrict__ b,
                             const float* __restrict__ m, const float* __restrict__ v)
{
    __shared__ float t[32][33];
    int c0 = blockIdx.x * 32, hw0 = blockIdx.y * 32, bb = blockIdx.z;
    int tx = threadIdx.x, ty = threadIdx.y;
#pragma unroll
    for (int i = 0; i < 4; i++) {
        int c = c0 + ty + i * 8;
        float s  = g[c] * rsqrtf(v[c] + EPSV);
        float sh = b[c] - m[c] * s;
        float val = x[((size_t)bb * CD + c) * HWD + hw0 + tx] * s + sh;
        g_xbn[(size_t)c * NCOL + bb * HWD + hw0 + tx] = val;
        t[ty + i * 8][tx] = val;
    }
    __syncthreads();
#pragma unroll
    for (int i = 0; i < 4; i++) {
        float val = t[tx][ty + i * 8];
        int n = bb * HWD + hw0 + ty + i * 8;
        bf16 h = __float2bfloat16_rn(val);
        g_xth[(size_t)n * CD + c0 + tx] = h;
        g_xtl[(size_t)n * CD + c0 + tx] = __float2bfloat16_rn(val - __bfloat162float(h));
    }
}

// ---------------- generic transpose + split: src[C][NCOL] f32 -> dh/dl[NCOL][C] bf16 ----------------
__global__ void tsplit_kernel(const float* __restrict__ src, bf16* __restrict__ dh,
                              bf16* __restrict__ dl, int C)
{
    __shared__ float t[32][33];
    int c0 = blockIdx.x * 32, col0 = blockIdx.y * 32;
    int tx = threadIdx.x, ty = threadIdx.y;
#pragma unroll
    for (int i = 0; i < 4; i++)
        t[ty + i * 8][tx] = src[(size_t)(c0 + ty + i * 8) * NCOL + col0 + tx];
    __syncthreads();
#pragma unroll
    for (int i = 0; i < 4; i++) {
        float val = t[tx][ty + i * 8];
        int n = col0 + ty + i * 8;
        bf16 h = __float2bfloat16_rn(val);
        dh[(size_t)n * C + c0 + tx] = h;
        dl[(size_t)n * C + c0 + tx] = __float2bfloat16_rn(val - __bfloat162float(h));
    }
}

// ---------------- weight hi/lo split ----------------
__global__ void wsplit_kernel(const float* __restrict__ src, bf16* __restrict__ dh,
                              bf16* __restrict__ dl, int n4)
{
    int i = blockIdx.x * blockDim.x + threadIdx.x;
    if (i >= n4) return;
    float4 v = ((const float4*)src)[i];
    bf16 h0 = __float2bfloat16_rn(v.x), h1 = __float2bfloat16_rn(v.y);
    bf16 h2 = __float2bfloat16_rn(v.z), h3 = __float2bfloat16_rn(v.w);
    bf16 l0 = __float2bfloat16_rn(v.x - __bfloat162float(h0));
    bf16 l1 = __float2bfloat16_rn(v.y - __bfloat162float(h1));
    bf16 l2 = __float2bfloat16_rn(v.z - __bfloat162float(h2));
    bf16 l3 = __float2bfloat16_rn(v.w - __bfloat162float(h3));
    uint2 ph, pl;
    ph.x = ((uint32_t)__bfloat16_as_ushort(h1) << 16) | __bfloat16_as_ushort(h0);
    ph.y = ((uint32_t)__bfloat16_as_ushort(h3) << 16) | __bfloat16_as_ushort(h2);
    pl.x = ((uint32_t)__bfloat16_as_ushort(l1) << 16) | __bfloat16_as_ushort(l0);
    pl.y = ((uint32_t)__bfloat16_as_ushort(l3) << 16) | __bfloat16_as_ushort(l2);
    ((uint2*)dh)[i] = ph;
    ((uint2*)dl)[i] = pl;
}

__global__ void concat_bias_kernel(const float* __restrict__ a, const float* __restrict__ c,
                                   const float* __restrict__ e)
{
    int i = blockIdx.x * blockDim.x + threadIdx.x;
    if (i >= CD) return;
    g_bqkv[i] = a[i];
    g_bqkv[CD + i] = c[i];
    g_bqkv[2 * CD + i] = e[i];
}

// ---------------- warp-MMA split-bf16 GEMM ----------------
// D(M, 512) = [Ah+Al](M,K) @ [Bh+Bl](512,K)^T + bias, fp32 accumulate.
// Tiles: BM x BN, BK=32, 3-stage cp.async pipeline, 8 warps.
// Smem per operand: rows x 40 bf16 (80B stride -> conflict-free ldmatrix).
// EPI 0: +bias -> Y[m][NCOL]      (QKV)
// EPI 1: ReLU6(+bias) -> Y fp32   (MLP1)
// EPI 2: +bias +res -> (B,C,HW)   (MLP2)
template <int BM, int BN, int EPI>
__global__ void __launch_bounds__(256) gemm_mma(
    const bf16* __restrict__ Ah, const bf16* __restrict__ Al,
    const bf16* __restrict__ Bh, const bf16* __restrict__ Bl,
    const float* __restrict__ bias, float* __restrict__ Y,
    const float* __restrict__ res, int K)
{
    constexpr int ABYT  = BM * 80;            // one A operand bytes (stride 40 bf16)
    constexpr int BBYT  = BN * 80;            // one B operand bytes
    constexpr int STAGE = 2 * ABYT + 2 * BBYT;
    constexpr int WM = BM / 32;               // warps along m
    constexpr int WN = 8 / WM;                // warps along n
    constexpr int NI = (BN / WN) / 8;         // 8-wide n tiles per warp

    extern __shared__ __align__(16) char dsm[];
    const uint32_t sbase = smem_u32(dsm);

    const int tid  = threadIdx.x;
    const int wid  = tid >> 5;
    const int lane = tid & 31;
    const int wm   = wid % WM;
    const int wn   = wid / WM;
    const int m0   = blockIdx.x * BM;
    const int n0   = blockIdx.y * BN;

    const bf16* pAh = Ah + (size_t)m0 * K;
    const bf16* pAl = Al + (size_t)m0 * K;
    const bf16* pBh = Bh + (size_t)n0 * K;
    const bf16* pBl = Bl + (size_t)n0 * K;

    float acc[2][NI][4];
#pragma unroll
    for (int mi = 0; mi < 2; mi++)
#pragma unroll
        for (int ni = 0; ni < NI; ni++)
#pragma unroll
            for (int j = 0; j < 4; j++) acc[mi][ni][j] = 0.f;

    const int nch = K >> 5;   // 32-wide k chunks

    auto load_stage = [&](int slot, int ko) {
        const uint32_t st = sbase + slot * STAGE;
        for (int i = tid; i < BM * 4; i += 256) {
            int row = i >> 2, seg = i & 3;
            cp_async16(st + row * 80 + seg * 16, pAh + (size_t)row * K + ko + seg * 8);
        }
        for (int i = tid; i < BM * 4; i += 256) {
            int row = i >> 2, seg = i & 3;
            cp_async16(st + ABYT + row * 80 + seg * 16, pAl + (size_t)row * K + ko + seg * 8);
        }
        for (int i = tid; i < BN * 4; i += 256) {
            int row = i >> 2, seg = i & 3;
            cp_async16(st + 2 * ABYT + row * 80 + seg * 16, pBh + (size_t)row * K + ko + seg * 8);
        }
        for (int i = tid; i < BN * 4; i += 256) {
            int row = i >> 2, seg = i & 3;
            cp_async16(st + 2 * ABYT + BBYT + row * 80 + seg * 16, pBl + (size_t)row * K + ko + seg * 8);
        }
    };

    load_stage(0, 0);  cp_commit();
    load_stage(1, 32); cp_commit();

    const int lrow = (lane & 7) + ((lane >> 3) & 1) * 8;   // row within 16-row tile
    const int lcol = (lane >> 4) * 8;                      // k sub-block 0/8

    int slot = 0;
    for (int ch = 0; ch < nch; ch++) {
        if (ch + 2 < nch) load_stage((ch + 2) % 3, (ch + 2) * 32);
        cp_commit();                 // always commit: keeps wait-count exact at the tail
        cp_wait2();
        __syncthreads();
        const uint32_t st = sbase + slot * STAGE;
        slot = (slot == 2) ? 0 : slot + 1;

#pragma unroll
        for (int ks = 0; ks < 32; ks += 16) {
            uint32_t ah[2][4], al[2][4];
#pragma unroll
            for (int mi = 0; mi < 2; mi++) {
                uint32_t addr = st + (wm * 32 + mi * 16 + lrow) * 80 + (ks + lcol) * 2;
                LDSM4(ah[mi], addr);
                LDSM4(al[mi], addr + ABYT);
            }
            uint32_t bh[NI][2], bl[NI][2];
#pragma unroll
            for (int np = 0; np < NI / 2; np++) {
                uint32_t addr = st + 2 * ABYT + (wn * (NI * 8) + np * 16 + lrow) * 80 + (ks + lcol) * 2;
                uint32_t r[4];
                LDSM4(r, addr);
                bh[2 * np][0] = r[0]; bh[2 * np][1] = r[2];
                bh[2 * np + 1][0] = r[1]; bh[2 * np + 1][1] = r[3];
                LDSM4(r, addr + BBYT);
                bl[2 * np][0] = r[0]; bl[2 * np][1] = r[2];
                bl[2 * np + 1][0] = r[1]; bl[2 * np + 1][1] = r[3];
            }
#pragma unroll
            for (int mi = 0; mi < 2; mi++)
#pragma unroll
                for (int ni = 0; ni < NI; ni++) {
                    MMA16816(acc[mi][ni], ah[mi], bh[ni]);
                    MMA16816(acc[mi][ni], ah[mi], bl[ni]);
                    MMA16816(acc[mi][ni], al[mi], bh[ni]);
                }
        }
        __syncthreads();
    }

    // ---- epilogue ----
#pragma unroll
    for (int mi = 0; mi < 2; mi++) {
        int r0 = m0 + wm * 32 + mi * 16 + (lane >> 2);
        float bv0 = bias[r0], bv1 = bias[r0 + 8];
#pragma unroll
        for (int ni = 0; ni < NI; ni++) {
            int c = n0 + wn * (NI * 8) + ni * 8 + (lane & 3) * 2;
            float* a = acc[mi][ni];
            if (EPI == 0 || EPI == 1) {
                float2 v0 = make_float2(a[0] + bv0, a[1] + bv0);
                float2 v1 = make_float2(a[2] + bv1, a[3] + bv1);
                if (EPI == 1) {
                    v0.x = fminf(fmaxf(v0.x, 0.f), 6.f);
                    v0.y = fminf(fmaxf(v0.y, 0.f), 6.f);
                    v1.x = fminf(fmaxf(v1.x, 0.f), 6.f);
                    v1.y = fminf(fmaxf(v1.y, 0.f), 6.f);
                }
                *(float2*)(Y + (size_t)r0 * NCOL + c) = v0;
                *(float2*)(Y + (size_t)(r0 + 8) * NCOL + c) = v1;
            } else {
                int bb = c >> 8, hw = c & 255;
                const float* rp0 = res + (size_t)r0 * NCOL + c;
                const float* rp1 = res + (size_t)(r0 + 8) * NCOL + c;
                float2 v0 = make_float2(a[0] + bv0 + rp0[0], a[1] + bv0 + rp0[1]);
                float2 v1 = make_float2(a[2] + bv1 + rp1[0], a[3] + bv1 + rp1[1]);
                *(float2*)(Y + ((size_t)bb * CD + r0) * HWD + hw) = v0;
                *(float2*)(Y + ((size_t)bb * CD + r0 + 8) * HWD + hw) = v1;
            }
        }
    }
}

// ---------------- fused attention (fp32, collapsed keys), 32-query tiles ----------------
#define SPS 257
#define SMEM_ATTN ((32 * SPS + 16 * 68 + 16 * 260) * 4)

__global__ void attn_kernel()
{
    extern __shared__ float sm[];
    float* sP = sm;                        // 32 x SPS
    float* sQ = sm + 32 * SPS;             // 16 x 36 (phase 1) / 16 x 68 as sV (phase 2)
    float* sK = sQ + 16 * 68;              // 16 x 260
    float* sV = sQ;

    const int bn = blockIdx.x;
    const int b  = bn >> 3;
    const int n  = bn & 7;
    const int q0 = blockIdx.y * 32;
    const int tid = threadIdx.x;
    const int tx = tid & 15;
    const int ty = tid >> 4;

    const float* qh = g_qkv + (size_t)n * HD * NCOL + b * HWD;
    const float* kh = g_qkv + (size_t)CD * NCOL + (size_t)n * HD * NCOL + b * HWD;
    const float* vh = g_qkv + (size_t)2 * CD * NCOL + (size_t)n * HD * NCOL + b * HWD;

    // ---- phase 1: energy E[q=ty*2+i][s=j*16+tx] ----
    float acc[2][16];
#pragma unroll
    for (int i = 0; i < 2; i++)
#pragma unroll
        for (int j = 0; j < 16; j++) acc[i][j] = 0.f;

    for (int k0 = 0; k0 < HD; k0 += 16) {
        {   // Q tile 16x32
            int r = tid >> 4, c2 = tid & 15;
            float2 v2 = *(const float2*)(qh + (size_t)(k0 + r) * NCOL + q0 + c2 * 2);
            *(float2*)&sQ[r * 36 + c2 * 2] = v2;
        }
#pragma unroll
        for (int i = 0; i < 4; i++) {   // K tile 16x256
            int idx = i * 256 + tid;
            int r = idx >> 6, c4 = idx & 63;
            float4 v4 = *(const float4*)(kh + (size_t)(k0 + r) * NCOL + c4 * 4);
            *(float4*)&sK[r * 260 + c4 * 4] = v4;
        }
        __syncthreads();
#pragma unroll
        for (int kk = 0; kk < 16; kk++) {
            float rq[2];
            *(float2*)rq = *(float2*)&sQ[kk * 36 + ty * 2];
            float rs[16];
#pragma unroll
            for (int j = 0; j < 16; j++) rs[j] = sK[kk * 260 + j * 16 + tx];
#pragma unroll
            for (int i = 0; i < 2; i++)
#pragma unroll
                for (int j = 0; j < 16; j++) acc[i][j] += rq[i] * rs[j];
        }
        __syncthreads();
    }
#pragma unroll
    for (int i = 0; i < 2; i++) {
        int q = ty * 2 + i;
#pragma unroll
        for (int j = 0; j < 16; j++) {
            int s = j * 16 + tx;
            sP[q * SPS + s] = acc[i][j] + c_lw[s >> 4] + c_lw[s & 15];
        }
    }
    __syncthreads();

    // ---- softmax (8 warps x 4 rows) ----
    {
        int warp = tid >> 5, lane = tid & 31;
        for (int r = warp * 4; r < warp * 4 + 4; r++) {
            float* row = sP + r * SPS;
            float mx = -1e30f;
#pragma unroll
            for (int s = lane; s < 256; s += 32) mx = fmaxf(mx, row[s]);
#pragma unroll
            for (int o = 16; o > 0; o >>= 1) mx = fmaxf(mx, __shfl_xor_sync(0xffffffffu, mx, o));
            float sum = 0.f;
#pragma unroll
            for (int s = lane; s < 256; s += 32) {
                float e = __expf(row[s] - mx);
                row[s] = e;
                sum += e;
            }
#pragma unroll
            for (int o = 16; o > 0; o >>= 1) sum += __shfl_xor_sync(0xffffffffu, sum, o);
            float inv = 1.f / sum;
#pragma unroll
            for (int s = lane; s < 256; s += 32) row[s] *= inv;
        }
    }
    __syncthreads();

    // ---- phase 2: O[h][q] = sum_s V[h][s] * P[q][s] ----
    float* ao = g_ao + (size_t)n * HD * NCOL + b * HWD;
    for (int h0 = 0; h0 < HD; h0 += 64) {
        float acc2[4][2];
#pragma unroll
        for (int i = 0; i < 4; i++)
#pragma unroll
            for (int j = 0; j < 2; j++) acc2[i][j] = 0.f;

        for (int s0 = 0; s0 < 256; s0 += 16) {
            {   // V tile 64h x 16s, transposed to sV[s][h]
                int hr = tid >> 2, s4 = tid & 3;
                float4 v4 = *(const float4*)(vh + (size_t)(h0 + hr) * NCOL + s0 + s4 * 4);
                sV[(s4 * 4 + 0) * 68 + hr] = v4.x;
                sV[(s4 * 4 + 1) * 68 + hr] = v4.y;
                sV[(s4 * 4 + 2) * 68 + hr] = v4.z;
                sV[(s4 * 4 + 3) * 68 + hr] = v4.w;
            }
            __syncthreads();
#pragma unroll
            for (int sl = 0; sl < 16; sl++) {
                float rv[4];
                *(float4*)rv = *(float4*)&sV[sl * 68 + ty * 4];
                float rp[2];
#pragma unroll
                for (int j = 0; j < 2; j++) rp[j] = sP[(tx * 2 + j) * SPS + s0 + sl];
#pragma unroll
                for (int i = 0; i < 4; i++)
#pragma unroll
                    for (int j = 0; j < 2; j++) acc2[i][j] += rv[i] * rp[j];
            }
            __syncthreads();
        }
#pragma unroll
        for (int i = 0; i < 4; i++) {
            int h = h0 + ty * 4 + i;
            float2 ov = make_float2(acc2[i][0], acc2[i][1]);
            *(float2*)(ao + (size_t)h * NCOL + q0 + tx * 2) = ov;
        }
    }
}

// ---------------- combine: x1 = x + xbn + gamma*ao ; BN2 -> transposed hi/lo ----------------
__global__ void combine_t_kernel(const float* __restrict__ x, const float* __restrict__ gamma,
                                 const float* __restrict__ g2, const float* __restrict__ b2,
                                 const float* __restrict__ m2, const float* __restrict__ v2)
{
    __shared__ float t[32][33];
    int c0 = blockIdx.x * 32, col0 = blockIdx.y * 32;
    int tx = threadIdx.x, ty = threadIdx.y;
    int col = col0 + tx;
    int bb = col >> 8, hw = col & 255;
    float gm = gamma[0];
#pragma unroll
    for (int i = 0; i < 4; i++) {
        int c = c0 + ty + i * 8;
        size_t idx = (size_t)c * NCOL + col;
        float x1 = x[((size_t)bb * CD + c) * HWD + hw] + g_xbn[idx] + gm * g_ao[idx];
        g_x1[idx] = x1;
        float s = g2[c] * rsqrtf(v2[c] + EPSV);
        t[ty + i * 8][tx] = x1 * s + (b2[c] - m2[c] * s);
    }
    __syncthreads();
#pragma unroll
    for (int i = 0; i < 4; i++) {
        float val = t[tx][ty + i * 8];
        int n = col0 + ty + i * 8;
        bf16 h = __float2bfloat16_rn(val);
        g_xt2h[(size_t)n * CD + c0 + tx] = h;
        g_xt2l[(size_t)n * CD + c0 + tx] = __float2bfloat16_rn(val - __bfloat162float(h));
    }
}

// ---------------- launch ----------------
extern "C" void kernel_launch(void* const* d_in, const int* in_sizes, int n_in,
                              void* d_out, int out_size)
{
    const float* x     = (const float*)d_in[0];
    const float* bn1_g = (const float*)d_in[1];
    const float* bn1_b = (const float*)d_in[2];
    const float* bn1_m = (const float*)d_in[3];
    const float* bn1_v = (const float*)d_in[4];
    const float* Wq    = (const float*)d_in[5];
    const float* bq    = (const float*)d_in[6];
    const float* Wk    = (const float*)d_in[7];
    const float* bk    = (const float*)d_in[8];
    const float* Wv    = (const float*)d_in[9];
    const float* bv    = (const float*)d_in[10];
    const float* gamma = (const float*)d_in[11];
    const float* bn2_g = (const float*)d_in[12];
    const float* bn2_b = (const float*)d_in[13];
    const float* bn2_m = (const float*)d_in[14];
    const float* bn2_v = (const float*)d_in[15];
    const float* W1    = (const float*)d_in[16];
    const float* b1    = (const float*)d_in[17];
    const float* W2    = (const float*)d_in[18];
    const float* b2    = (const float*)d_in[19];
    float* out = (float*)d_out;

    bf16 *p_wh, *p_wl, *p_w1h, *p_w1l, *p_w2h, *p_w2l, *p_xth, *p_xtl, *p_x2h, *p_x2l, *p_hth, *p_htl;
    float *p_bqkv, *p_qkv, *p_x1, *p_h;
    cudaGetSymbolAddress((void**)&p_wh,  g_wh);
    cudaGetSymbolAddress((void**)&p_wl,  g_wl);
    cudaGetSymbolAddress((void**)&p_w1h, g_w1h);
    cudaGetSymbolAddress((void**)&p_w1l, g_w1l);
    cudaGetSymbolAddress((void**)&p_w2h, g_w2h);
    cudaGetSymbolAddress((void**)&p_w2l, g_w2l);
    cudaGetSymbolAddress((void**)&p_xth, g_xth);
    cudaGetSymbolAddress((void**)&p_xtl, g_xtl);
    cudaGetSymbolAddress((void**)&p_x2h, g_xt2h);
    cudaGetSymbolAddress((void**)&p_x2l, g_xt2l);
    cudaGetSymbolAddress((void**)&p_hth, g_hth);
    cudaGetSymbolAddress((void**)&p_htl, g_htl);
    cudaGetSymbolAddress((void**)&p_bqkv, g_bqkv);
    cudaGetSymbolAddress((void**)&p_qkv, g_qkv);
    cudaGetSymbolAddress((void**)&p_x1,  g_x1);
    cudaGetSymbolAddress((void**)&p_h,   g_h);

    constexpr int SMQKV = 3 * (2 * 128 * 80 + 2 * 128 * 80);  // 122880
    constexpr int SMM1  = 3 * (2 * 64 * 80 + 2 * 64 * 80);    //  61440
    constexpr int SMM2  = 3 * (2 * 64 * 80 + 2 * 128 * 80);   //  92160
    cudaFuncSetAttribute(gemm_mma<128, 128, 0>, cudaFuncAttributeMaxDynamicSharedMemorySize, SMQKV);
    cudaFuncSetAttribute(gemm_mma<64, 64, 1>,   cudaFuncAttributeMaxDynamicSharedMemorySize, SMM1);
    cudaFuncSetAttribute(gemm_mma<64, 128, 2>,  cudaFuncAttributeMaxDynamicSharedMemorySize, SMM2);
    cudaFuncSetAttribute(attn_kernel, cudaFuncAttributeMaxDynamicSharedMemorySize, SMEM_ATTN);

    // launches 1-5 (so launch #6 = QKV GEMM lands in the ncu -s 5 -c 1 window)
    wsplit_kernel<<<(CD * CD / 4 + 255) / 256, 256>>>(Wq, p_wh, p_wl, CD * CD / 4);
    wsplit_kernel<<<(CD * CD / 4 + 255) / 256, 256>>>(Wk, p_wh + (size_t)CD * CD, p_wl + (size_t)CD * CD, CD * CD / 4);
    wsplit_kernel<<<(CD * CD / 4 + 255) / 256, 256>>>(Wv, p_wh + (size_t)2 * CD * CD, p_wl + (size_t)2 * CD * CD, CD * CD / 4);
    bn1_t_kernel<<<dim3(CD / 32, HWD / 32, 2), dim3(32, 8)>>>(x, bn1_g, bn1_b, bn1_m, bn1_v);
    concat_bias_kernel<<<CD / 256, 256>>>(bq, bk, bv);

    // QKV fused projection: M = 6144, N = 512, K = 2048
    gemm_mma<128, 128, 0><<<dim3(48, 4), 256, SMQKV>>>(p_wh, p_wl, p_xth, p_xtl, p_bqkv, p_qkv, nullptr, CD);

    // attention (collapsed keys + log-multiplicity bias), 128 CTAs
    attn_kernel<<<dim3(16, 8), 256, SMEM_ATTN>>>();

    // residual + BN2 (+ transpose + split)
    combine_t_kernel<<<dim3(CD / 32, NCOL / 32), dim3(32, 8)>>>(x, gamma, bn2_g, bn2_b, bn2_m, bn2_v);

    // MLP weight splits
    wsplit_kernel<<<(HID * CD / 4 + 255) / 256, 256>>>(W1, p_w1h, p_w1l, HID * CD / 4);
    wsplit_kernel<<<(CD * HID / 4 + 255) / 256, 256>>>(W2, p_w2h, p_w2l, CD * HID / 4);

    // MLP1: 512 x 512, K=2048, ReLU6 -> fp32 hidden (64 CTAs)
    gemm_mma<64, 64, 1><<<dim3(HID / 64, NCOL / 64), 256, SMM1>>>(p_w1h, p_w1l, p_x2h, p_x2l, b1, p_h, nullptr, CD);

    // hidden transpose + split
    tsplit_kernel<<<dim3(HID / 32, NCOL / 32), dim3(32, 8)>>>(p_h, p_hth, p_htl, HID);

    // MLP2: 2048 x 512, K=512, +residual, NCHW out (128 CTAs)
    gemm_mma<64, 128, 2><<<dim3(CD / 64, NCOL / 128), 256, SMM2>>>(p_w2h, p_w2l, p_hth, p_htl, b2, out, p_x1, HID);
}

// round 6
// speedup vs baseline: 2.6221x; 1.1794x over previous
#include <cuda_runtime.h>
#include <cuda_bf16.h>
#include <cstdint>
#include <math.h>

#define CD    2048
#define NCOL  512
#define HWD   256
#define HD    256
#define HID   512
#define EPSV  1e-5f

typedef __nv_bfloat16 bf16;

// ---------------- device scratch ----------------
__device__ float g_xbn [CD * NCOL];            // BN1 output, [C][NCOL] fp32
__device__ bf16  g_xth [NCOL * CD];            // BN1 output transposed hi (row n, col c)
__device__ bf16  g_xtl [NCOL * CD];
__device__ bf16  g_wh  [3 * CD * CD];          // Wq|Wk|Wv hi (row m, col k)
__device__ bf16  g_wl  [3 * CD * CD];
__device__ bf16  g_w1h [HID * CD];
__device__ bf16  g_w1l [HID * CD];
__device__ bf16  g_w2h [CD * HID];
__device__ bf16  g_w2l [CD * HID];
__device__ float g_qkv [3 * CD * NCOL];        // q|k|v fp32 [3C][NCOL]
__device__ float g_ao  [CD * NCOL];
__device__ float g_x1  [CD * NCOL];
__device__ bf16  g_xt2h[NCOL * CD];            // BN2 output transposed hi
__device__ bf16  g_xt2l[NCOL * CD];
__device__ float g_h   [HID * NCOL];           // MLP hidden fp32
__device__ bf16  g_hth [NCOL * HID];           // hidden transposed hi
__device__ bf16  g_htl [NCOL * HID];

// log key multiplicity (separable reflect-pad collapse)
__constant__ float c_lw[16] = {
    1.6094379124341003f, 2.3025850929940460f, 2.3025850929940460f, 2.3025850929940460f,
    2.1972245773362196f, 2.0794415416798357f, 2.0794415416798357f, 2.0794415416798357f,
    2.0794415416798357f, 2.0794415416798357f, 2.0794415416798357f, 2.1972245773362196f,
    2.3025850929940460f, 2.3025850929940460f, 2.3025850929940460f, 1.6094379124341003f
};

// ---------------- PTX helpers (sm_80-compatible only) ----------------
__device__ __forceinline__ uint32_t smem_u32(const void* p) {
    uint32_t a;
    asm("{ .reg .u64 t; cvta.to.shared.u64 t, %1; cvt.u32.u64 %0, t; }" : "=r"(a) : "l"(p));
    return a;
}
__device__ __forceinline__ void cp_async16(uint32_t sdst, const void* gsrc) {
    asm volatile("cp.async.cg.shared.global [%0], [%1], 16;" :: "r"(sdst), "l"(gsrc));
}
__device__ __forceinline__ void cp_commit() { asm volatile("cp.async.commit_group;"); }
__device__ __forceinline__ void cp_wait1()  { asm volatile("cp.async.wait_group 1;" ::: "memory"); }

#define LDSM4(r, addr) \
    asm volatile("ldmatrix.sync.aligned.m8n8.x4.shared.b16 {%0,%1,%2,%3}, [%4];" \
        : "=r"((r)[0]), "=r"((r)[1]), "=r"((r)[2]), "=r"((r)[3]) : "r"(addr))

#define MMA16816(d, a, b) \
    asm volatile("mma.sync.aligned.m16n8k16.row.col.f32.bf16.bf16.f32 " \
        "{%0,%1,%2,%3},{%4,%5,%6,%7},{%8,%9},{%0,%1,%2,%3};" \
        : "+f"((d)[0]), "+f"((d)[1]), "+f"((d)[2]), "+f"((d)[3]) \
        : "r"((a)[0]), "r"((a)[1]), "r"((a)[2]), "r"((a)[3]), "r"((b)[0]), "r"((b)[1]))

// ---------------- BN1 + transpose + bf16 split ----------------
__global__ void bn1_t_kernel(const float* __restrict__ x,
                             const float* __restrict__ g, const float* __restrict__ b,
                             const float* __restrict__ m, const float* __restrict__ v)
{
    __shared__ float t[32][33];
    int c0 = blockIdx.x * 32, hw0 = blockIdx.y * 32, bb = blockIdx.z;
    int tx = threadIdx.x, ty = threadIdx.y;
#pragma unroll
    for (int i = 0; i < 4; i++) {
        int c = c0 + ty + i * 8;
        float s  = g[c] * rsqrtf(v[c] + EPSV);
        float sh = b[c] - m[c] * s;
        float val = x[((size_t)bb * CD + c) * HWD + hw0 + tx] * s + sh;
        g_xbn[(size_t)c * NCOL + bb * HWD + hw0 + tx] = val;
        t[ty + i * 8][tx] = val;
    }
    __syncthreads();
#pragma unroll
    for (int i = 0; i < 4; i++) {
        float val = t[tx][ty + i * 8];
        int n = bb * HWD + hw0 + ty + i * 8;
        bf16 h = __float2bfloat16_rn(val);
        g_xth[(size_t)n * CD + c0 + tx] = h;
        g_xtl[(size_t)n * CD + c0 + tx] = __float2bfloat16_rn(val - __bfloat162float(h));
    }
}

// ---------------- generic transpose + split: src[C][NCOL] f32 -> dh/dl[NCOL][C] bf16 ----------------
__global__ void tsplit_kernel(const float* __restrict__ src, bf16* __restrict__ dh,
                              bf16* __restrict__ dl, int C)
{
    __shared__ float t[32][33];
    int c0 = blockIdx.x * 32, col0 = blockIdx.y * 32;
    int tx = threadIdx.x, ty = threadIdx.y;
#pragma unroll
    for (int i = 0; i < 4; i++)
        t[ty + i * 8][tx] = src[(size_t)(c0 + ty + i * 8) * NCOL + col0 + tx];
    __syncthreads();
#pragma unroll
    for (int i = 0; i < 4; i++) {
        float val = t[tx][ty + i * 8];
        int n = col0 + ty + i * 8;
        bf16 h = __float2bfloat16_rn(val);
        dh[(size_t)n * C + c0 + tx] = h;
        dl[(size_t)n * C + c0 + tx] = __float2bfloat16_rn(val - __bfloat162float(h));
    }
}

// ---------------- weight hi/lo split (vector core) ----------------
__device__ __forceinline__ void split4(const float* __restrict__ src, bf16* __restrict__ dh,
                                       bf16* __restrict__ dl, int i)
{
    float4 v = ((const float4*)src)[i];
    bf16 h0 = __float2bfloat16_rn(v.x), h1 = __float2bfloat16_rn(v.y);
    bf16 h2 = __float2bfloat16_rn(v.z), h3 = __float2bfloat16_rn(v.w);
    bf16 l0 = __float2bfloat16_rn(v.x - __bfloat162float(h0));
    bf16 l1 = __float2bfloat16_rn(v.y - __bfloat162float(h1));
    bf16 l2 = __float2bfloat16_rn(v.z - __bfloat162float(h2));
    bf16 l3 = __float2bfloat16_rn(v.w - __bfloat162float(h3));
    uint2 ph, pl;
    ph.x = ((uint32_t)__bfloat16_as_ushort(h1) << 16) | __bfloat16_as_ushort(h0);
    ph.y = ((uint32_t)__bfloat16_as_ushort(h3) << 16) | __bfloat16_as_ushort(h2);
    pl.x = ((uint32_t)__bfloat16_as_ushort(l1) << 16) | __bfloat16_as_ushort(l0);
    pl.y = ((uint32_t)__bfloat16_as_ushort(l3) << 16) | __bfloat16_as_ushort(l2);
    ((uint2*)dh)[i] = ph;
    ((uint2*)dl)[i] = pl;
}

// QKV weights: 3 sources -> one contiguous hi/lo pair
__global__ void wsplit3_kernel(const float* __restrict__ a, const float* __restrict__ b,
                               const float* __restrict__ c)
{
    const int n4 = CD * CD / 4;
    int w = blockIdx.y;
    const float* src = (w == 0) ? a : (w == 1) ? b : c;
    bf16* dh = g_wh + (size_t)w * CD * CD;
    bf16* dl = g_wl + (size_t)w * CD * CD;
    int i = blockIdx.x * blockDim.x + threadIdx.x;
    if (i < n4) split4(src, dh, dl, i);
}

// MLP weights: W1 and W2 (equal element counts)
__global__ void wsplit2_kernel(const float* __restrict__ a, const float* __restrict__ b)
{
    const int n4 = HID * CD / 4;
    int w = blockIdx.y;
    const float* src = (w == 0) ? a : b;
    bf16* dh = (w == 0) ? g_w1h : g_w2h;
    bf16* dl = (w == 0) ? g_w1l : g_w2l;
    int i = blockIdx.x * blockDim.x + threadIdx.x;
    if (i < n4) split4(src, dh, dl, i);
}

// ---------------- warp-MMA split-bf16 GEMM ----------------
// D(M, 512) = [Ah+Al](M,K) @ [Bh+Bl](512,K)^T + bias, fp32 accumulate.
// Tiles: BM x BN, BK=32, 2-stage cp.async pipeline, 8 warps, 2 CTAs/SM.
// EPI 0: + per-segment bias (bq|bk|bv by m>>11) -> Y[m][NCOL]   (QKV)
// EPI 1: ReLU6(+bias) -> Y fp32                                  (MLP1)
// EPI 2: +bias +res -> (B,C,HW)                                  (MLP2)
template <int BM, int BN, int EPI>
__global__ void __launch_bounds__(256, 2) gemm_mma(
    const bf16* __restrict__ Ah, const bf16* __restrict__ Al,
    const bf16* __restrict__ Bh, const bf16* __restrict__ Bl,
    const float* __restrict__ bias, const float* __restrict__ bias2,
    const float* __restrict__ bias3, float* __restrict__ Y,
    const float* __restrict__ res, int K)
{
    constexpr int ABYT  = BM * 80;            // one A operand bytes (stride 40 bf16)
    constexpr int BBYT  = BN * 80;            // one B operand bytes
    constexpr int STAGE = 2 * ABYT + 2 * BBYT;
    constexpr int WM = BM / 32;               // warps along m
    constexpr int WN = 8 / WM;                // warps along n
    constexpr int NI = (BN / WN) / 8;         // 8-wide n tiles per warp

    extern __shared__ __align__(16) char dsm[];
    const uint32_t sbase = smem_u32(dsm);

    const int tid  = threadIdx.x;
    const int wid  = tid >> 5;
    const int lane = tid & 31;
    const int wm   = wid % WM;
    const int wn   = wid / WM;
    const int m0   = blockIdx.x * BM;
    const int n0   = blockIdx.y * BN;

    const bf16* pAh = Ah + (size_t)m0 * K;
    const bf16* pAl = Al + (size_t)m0 * K;
    const bf16* pBh = Bh + (size_t)n0 * K;
    const bf16* pBl = Bl + (size_t)n0 * K;

    float acc[2][NI][4];
#pragma unroll
    for (int mi = 0; mi < 2; mi++)
#pragma unroll
        for (int ni = 0; ni < NI; ni++)
#pragma unroll
            for (int j = 0; j < 4; j++) acc[mi][ni][j] = 0.f;

    const int nch = K >> 5;   // 32-wide k chunks

    auto load_stage = [&](int slot, int ko) {
        const uint32_t st = sbase + slot * STAGE;
        for (int i = tid; i < BM * 4; i += 256) {
            int row = i >> 2, seg = i & 3;
            cp_async16(st + row * 80 + seg * 16, pAh + (size_t)row * K + ko + seg * 8);
        }
        for (int i = tid; i < BM * 4; i += 256) {
            int row = i >> 2, seg = i & 3;
            cp_async16(st + ABYT + row * 80 + seg * 16, pAl + (size_t)row * K + ko + seg * 8);
        }
        for (int i = tid; i < BN * 4; i += 256) {
            int row = i >> 2, seg = i & 3;
            cp_async16(st + 2 * ABYT + row * 80 + seg * 16, pBh + (size_t)row * K + ko + seg * 8);
        }
        for (int i = tid; i < BN * 4; i += 256) {
            int row = i >> 2, seg = i & 3;
            cp_async16(st + 2 * ABYT + BBYT + row * 80 + seg * 16, pBl + (size_t)row * K + ko + seg * 8);
        }
    };

    load_stage(0, 0); cp_commit();

    const int lrow = (lane & 7) + ((lane >> 3) & 1) * 8;   // row within 16-row tile
    const int lcol = (lane >> 4) * 8;                      // k sub-block 0/8

    for (int ch = 0; ch < nch; ch++) {
        if (ch + 1 < nch) load_stage((ch + 1) & 1, (ch + 1) * 32);
        cp_commit();                 // always commit -> wait count stays exact
        cp_wait1();
        __syncthreads();
        const uint32_t st = sbase + (ch & 1) * STAGE;

#pragma unroll
        for (int ks = 0; ks < 32; ks += 16) {
            uint32_t ah[2][4], al[2][4];
#pragma unroll
            for (int mi = 0; mi < 2; mi++) {
                uint32_t addr = st + (wm * 32 + mi * 16 + lrow) * 80 + (ks + lcol) * 2;
                LDSM4(ah[mi], addr);
                LDSM4(al[mi], addr + ABYT);
            }
            uint32_t bh[NI][2], bl[NI][2];
#pragma unroll
            for (int np = 0; np < NI / 2; np++) {
                uint32_t addr = st + 2 * ABYT + (wn * (NI * 8) + np * 16 + lrow) * 80 + (ks + lcol) * 2;
                uint32_t r[4];
                LDSM4(r, addr);
                bh[2 * np][0] = r[0]; bh[2 * np][1] = r[2];
                bh[2 * np + 1][0] = r[1]; bh[2 * np + 1][1] = r[3];
                LDSM4(r, addr + BBYT);
                bl[2 * np][0] = r[0]; bl[2 * np][1] = r[2];
                bl[2 * np + 1][0] = r[1]; bl[2 * np + 1][1] = r[3];
            }
            // product-major: maximize independent MMAs between same-acc reuses
#pragma unroll
            for (int mi = 0; mi < 2; mi++)
#pragma unroll
                for (int ni = 0; ni < NI; ni++) MMA16816(acc[mi][ni], ah[mi], bh[ni]);
#pragma unroll
            for (int mi = 0; mi < 2; mi++)
#pragma unroll
                for (int ni = 0; ni < NI; ni++) MMA16816(acc[mi][ni], ah[mi], bl[ni]);
#pragma unroll
            for (int mi = 0; mi < 2; mi++)
#pragma unroll
                for (int ni = 0; ni < NI; ni++) MMA16816(acc[mi][ni], al[mi], bh[ni]);
        }
        __syncthreads();
    }

    // ---- epilogue ----
#pragma unroll
    for (int mi = 0; mi < 2; mi++) {
        int r0 = m0 + wm * 32 + mi * 16 + (lane >> 2);
        float bv0, bv1;
        if (EPI == 0) {
            int seg = r0 >> 11;         // 0..2, same for r0 and r0+8 (16-row tile within 2048 seg)
            const float* bp = (seg == 0) ? bias : (seg == 1) ? bias2 : bias3;
            int rloc = r0 & 2047;
            bv0 = bp[rloc]; bv1 = bp[rloc + 8];
        } else {
            bv0 = bias[r0]; bv1 = bias[r0 + 8];
        }
#pragma unroll
        for (int ni = 0; ni < NI; ni++) {
            int c = n0 + wn * (NI * 8) + ni * 8 + (lane & 3) * 2;
            float* a = acc[mi][ni];
            if (EPI == 0 || EPI == 1) {
                float2 v0 = make_float2(a[0] + bv0, a[1] + bv0);
                float2 v1 = make_float2(a[2] + bv1, a[3] + bv1);
                if (EPI == 1) {
                    v0.x = fminf(fmaxf(v0.x, 0.f), 6.f);
                    v0.y = fminf(fmaxf(v0.y, 0.f), 6.f);
                    v1.x = fminf(fmaxf(v1.x, 0.f), 6.f);
                    v1.y = fminf(fmaxf(v1.y, 0.f), 6.f);
                }
                *(float2*)(Y + (size_t)r0 * NCOL + c) = v0;
                *(float2*)(Y + (size_t)(r0 + 8) * NCOL + c) = v1;
            } else {
                int bb = c >> 8, hw = c & 255;
                const float* rp0 = res + (size_t)r0 * NCOL + c;
                const float* rp1 = res + (size_t)(r0 + 8) * NCOL + c;
                float2 v0 = make_float2(a[0] + bv0 + rp0[0], a[1] + bv0 + rp0[1]);
                float2 v1 = make_float2(a[2] + bv1 + rp1[0], a[3] + bv1 + rp1[1]);
                *(float2*)(Y + ((size_t)bb * CD + r0) * HWD + hw) = v0;
                *(float2*)(Y + ((size_t)bb * CD + r0 + 8) * HWD + hw) = v1;
            }
        }
    }
}

// ---------------- fused attention (fp32, collapsed keys), 32-query tiles ----------------
#define SPS 257
#define SMEM_ATTN ((32 * SPS + 16 * 68 + 16 * 260) * 4)

__global__ void attn_kernel()
{
    extern __shared__ float sm[];
    float* sP = sm;                        // 32 x SPS
    float* sQ = sm + 32 * SPS;             // 16 x 36 (phase 1) / 16 x 68 as sV (phase 2)
    float* sK = sQ + 16 * 68;              // 16 x 260
    float* sV = sQ;

    const int bn = blockIdx.x;
    const int b  = bn >> 3;
    const int n  = bn & 7;
    const int q0 = blockIdx.y * 32;
    const int tid = threadIdx.x;
    const int tx = tid & 15;
    const int ty = tid >> 4;

    const float* qh = g_qkv + (size_t)n * HD * NCOL + b * HWD;
    const float* kh = g_qkv + (size_t)CD * NCOL + (size_t)n * HD * NCOL + b * HWD;
    const float* vh = g_qkv + (size_t)2 * CD * NCOL + (size_t)n * HD * NCOL + b * HWD;

    float acc[2][16];
#pragma unroll
    for (int i = 0; i < 2; i++)
#pragma unroll
        for (int j = 0; j < 16; j++) acc[i][j] = 0.f;

    for (int k0 = 0; k0 < HD; k0 += 16) {
        {
            int r = tid >> 4, c2 = tid & 15;
            float2 v2 = *(const float2*)(qh + (size_t)(k0 + r) * NCOL + q0 + c2 * 2);
            *(float2*)&sQ[r * 36 + c2 * 2] = v2;
        }
#pragma unroll
        for (int i = 0; i < 4; i++) {
            int idx = i * 256 + tid;
            int r = idx >> 6, c4 = idx & 63;
            float4 v4 = *(const float4*)(kh + (size_t)(k0 + r) * NCOL + c4 * 4);
            *(float4*)&sK[r * 260 + c4 * 4] = v4;
        }
        __syncthreads();
#pragma unroll
        for (int kk = 0; kk < 16; kk++) {
            float rq[2];
            *(float2*)rq = *(float2*)&sQ[kk * 36 + ty * 2];
            float rs[16];
#pragma unroll
            for (int j = 0; j < 16; j++) rs[j] = sK[kk * 260 + j * 16 + tx];
#pragma unroll
            for (int i = 0; i < 2; i++)
#pragma unroll
                for (int j = 0; j < 16; j++) acc[i][j] += rq[i] * rs[j];
        }
        __syncthreads();
    }
#pragma unroll
    for (int i = 0; i < 2; i++) {
        int q = ty * 2 + i;
#pragma unroll
        for (int j = 0; j < 16; j++) {
            int s = j * 16 + tx;
            sP[q * SPS + s] = acc[i][j] + c_lw[s >> 4] + c_lw[s & 15];
        }
    }
    __syncthreads();

    {
        int warp = tid >> 5, lane = tid & 31;
        for (int r = warp * 4; r < warp * 4 + 4; r++) {
            float* row = sP + r * SPS;
            float mx = -1e30f;
#pragma unroll
            for (int s = lane; s < 256; s += 32) mx = fmaxf(mx, row[s]);
#pragma unroll
            for (int o = 16; o > 0; o >>= 1) mx = fmaxf(mx, __shfl_xor_sync(0xffffffffu, mx, o));
            float sum = 0.f;
#pragma unroll
            for (int s = lane; s < 256; s += 32) {
                float e = __expf(row[s] - mx);
                row[s] = e;
                sum += e;
            }
#pragma unroll
            for (int o = 16; o > 0; o >>= 1) sum += __shfl_xor_sync(0xffffffffu, sum, o);
            float inv = 1.f / sum;
#pragma unroll
            for (int s = lane; s < 256; s += 32) row[s] *= inv;
        }
    }
    __syncthreads();

    float* ao = g_ao + (size_t)n * HD * NCOL + b * HWD;
    for (int h0 = 0; h0 < HD; h0 += 64) {
        float acc2[4][2];
#pragma unroll
        for (int i = 0; i < 4; i++)
#pragma unroll
            for (int j = 0; j < 2; j++) acc2[i][j] = 0.f;

        for (int s0 = 0; s0 < 256; s0 += 16) {
            {
                int hr = tid >> 2, s4 = tid & 3;
                float4 v4 = *(const float4*)(vh + (size_t)(h0 + hr) * NCOL + s0 + s4 * 4);
                sV[(s4 * 4 + 0) * 68 + hr] = v4.x;
                sV[(s4 * 4 + 1) * 68 + hr] = v4.y;
                sV[(s4 * 4 + 2) * 68 + hr] = v4.z;
                sV[(s4 * 4 + 3) * 68 + hr] = v4.w;
            }
            __syncthreads();
#pragma unroll
            for (int sl = 0; sl < 16; sl++) {
                float rv[4];
                *(float4*)rv = *(float4*)&sV[sl * 68 + ty * 4];
                float rp[2];
#pragma unroll
                for (int j = 0; j < 2; j++) rp[j] = sP[(tx * 2 + j) * SPS + s0 + sl];
#pragma unroll
                for (int i = 0; i < 4; i++)
#pragma unroll
                    for (int j = 0; j < 2; j++) acc2[i][j] += rv[i] * rp[j];
            }
            __syncthreads();
        }
#pragma unroll
        for (int i = 0; i < 4; i++) {
            int h = h0 + ty * 4 + i;
            float2 ov = make_float2(acc2[i][0], acc2[i][1]);
            *(float2*)(ao + (size_t)h * NCOL + q0 + tx * 2) = ov;
        }
    }
}

// ---------------- combine: x1 = x + xbn + gamma*ao ; BN2 -> transposed hi/lo ----------------
__global__ void combine_t_kernel(const float* __restrict__ x, const float* __restrict__ gamma,
                                 const float* __restrict__ g2, const float* __restrict__ b2,
                                 const float* __restrict__ m2, const float* __restrict__ v2)
{
    __shared__ float t[32][33];
    int c0 = blockIdx.x * 32, col0 = blockIdx.y * 32;
    int tx = threadIdx.x, ty = threadIdx.y;
    int col = col0 + tx;
    int bb = col >> 8, hw = col & 255;
    float gm = gamma[0];
#pragma unroll
    for (int i = 0; i < 4; i++) {
        int c = c0 + ty + i * 8;
        size_t idx = (size_t)c * NCOL + col;
        float x1 = x[((size_t)bb * CD + c) * HWD + hw] + g_xbn[idx] + gm * g_ao[idx];
        g_x1[idx] = x1;
        float s = g2[c] * rsqrtf(v2[c] + EPSV);
        t[ty + i * 8][tx] = x1 * s + (b2[c] - m2[c] * s);
    }
    __syncthreads();
#pragma unroll
    for (int i = 0; i < 4; i++) {
        float val = t[tx][ty + i * 8];
        int n = col0 + ty + i * 8;
        bf16 h = __float2bfloat16_rn(val);
        g_xt2h[(size_t)n * CD + c0 + tx] = h;
        g_xt2l[(size_t)n * CD + c0 + tx] = __float2bfloat16_rn(val - __bfloat162float(h));
    }
}

// ---------------- launch ----------------
extern "C" void kernel_launch(void* const* d_in, const int* in_sizes, int n_in,
                              void* d_out, int out_size)
{
    const float* x     = (const float*)d_in[0];
    const float* bn1_g = (const float*)d_in[1];
    const float* bn1_b = (const float*)d_in[2];
    const float* bn1_m = (const float*)d_in[3];
    const float* bn1_v = (const float*)d_in[4];
    const float* Wq    = (const float*)d_in[5];
    const float* bq    = (const float*)d_in[6];
    const float* Wk    = (const float*)d_in[7];
    const float* bk    = (const float*)d_in[8];
    const float* Wv    = (const float*)d_in[9];
    const float* bv    = (const float*)d_in[10];
    const float* gamma = (const float*)d_in[11];
    const float* bn2_g = (const float*)d_in[12];
    const float* bn2_b = (const float*)d_in[13];
    const float* bn2_m = (const float*)d_in[14];
    const float* bn2_v = (const float*)d_in[15];
    const float* W1    = (const float*)d_in[16];
    const float* b1    = (const float*)d_in[17];
    const float* W2    = (const float*)d_in[18];
    const float* b2    = (const float*)d_in[19];
    float* out = (float*)d_out;

    bf16 *p_wh, *p_wl, *p_w1h, *p_w1l, *p_w2h, *p_w2l, *p_xth, *p_xtl, *p_x2h, *p_x2l, *p_hth, *p_htl;
    float *p_qkv, *p_x1, *p_h;
    cudaGetSymbolAddress((void**)&p_wh,  g_wh);
    cudaGetSymbolAddress((void**)&p_wl,  g_wl);
    cudaGetSymbolAddress((void**)&p_w1h, g_w1h);
    cudaGetSymbolAddress((void**)&p_w1l, g_w1l);
    cudaGetSymbolAddress((void**)&p_w2h, g_w2h);
    cudaGetSymbolAddress((void**)&p_w2l, g_w2l);
    cudaGetSymbolAddress((void**)&p_xth, g_xth);
    cudaGetSymbolAddress((void**)&p_xtl, g_xtl);
    cudaGetSymbolAddress((void**)&p_x2h, g_xt2h);
    cudaGetSymbolAddress((void**)&p_x2l, g_xt2l);
    cudaGetSymbolAddress((void**)&p_hth, g_hth);
    cudaGetSymbolAddress((void**)&p_htl, g_htl);
    cudaGetSymbolAddress((void**)&p_qkv, g_qkv);
    cudaGetSymbolAddress((void**)&p_x1,  g_x1);
    cudaGetSymbolAddress((void**)&p_h,   g_h);

    constexpr int SMQKV = 2 * (2 * 64 * 80 + 2 * 128 * 80);  // 61440
    constexpr int SMM1  = 2 * (2 * 64 * 80 + 2 * 64 * 80);   // 40960
    constexpr int SMM2  = SMQKV;
    cudaFuncSetAttribute(gemm_mma<64, 128, 0>, cudaFuncAttributeMaxDynamicSharedMemorySize, SMQKV);
    cudaFuncSetAttribute(gemm_mma<64, 64, 1>,  cudaFuncAttributeMaxDynamicSharedMemorySize, SMM1);
    cudaFuncSetAttribute(gemm_mma<64, 128, 2>, cudaFuncAttributeMaxDynamicSharedMemorySize, SMM2);
    cudaFuncSetAttribute(attn_kernel, cudaFuncAttributeMaxDynamicSharedMemorySize, SMEM_ATTN);

    // weight splits (2 launches) + BN1
    wsplit3_kernel<<<dim3((CD * CD / 4 + 255) / 256, 3), 256>>>(Wq, Wk, Wv);
    wsplit2_kernel<<<dim3((HID * CD / 4 + 255) / 256, 2), 256>>>(W1, W2);
    bn1_t_kernel<<<dim3(CD / 32, HWD / 32, 2), dim3(32, 8)>>>(x, bn1_g, bn1_b, bn1_m, bn1_v);

    // QKV fused projection: M = 6144, N = 512, K = 2048 (bias concat fused in epilogue)
    gemm_mma<64, 128, 0><<<dim3(96, 4), 256, SMQKV>>>(p_wh, p_wl, p_xth, p_xtl, bq, bk, bv, p_qkv, nullptr, CD);

    // attention (collapsed keys + log-multiplicity bias), 128 CTAs
    attn_kernel<<<dim3(16, 8), 256, SMEM_ATTN>>>();

    // residual + BN2 (+ transpose + split)
    combine_t_kernel<<<dim3(CD / 32, NCOL / 32), dim3(32, 8)>>>(x, gamma, bn2_g, bn2_b, bn2_m, bn2_v);

    // MLP1: 512 x 512, K=2048, ReLU6 -> fp32 hidden (64 CTAs)
    gemm_mma<64, 64, 1><<<dim3(HID / 64, NCOL / 64), 256, SMM1>>>(p_w1h, p_w1l, p_x2h, p_x2l, b1, nullptr, nullptr, p_h, nullptr, CD);

    // hidden transpose + split
    tsplit_kernel<<<dim3(HID / 32, NCOL / 32), dim3(32, 8)>>>(p_h, p_hth, p_htl, HID);

    // MLP2: 2048 x 512, K=512, +residual, NCHW out (128 CTAs)
    gemm_mma<64, 128, 2><<<dim3(CD / 64, NCOL / 128), 256, SMM2>>>(p_w2h, p_w2l, p_hth, p_htl, b2, nullptr, nullptr, out, p_x1, HID);
}